// round 11
// baseline (speedup 1.0000x reference)
#include <cuda_runtime.h>
#include <cuda_fp16.h>
#include <cstdint>

#define N_NODES 50000
#define N_EDGES 800000
#define B_GRAPH 8
#define HID 64
#define DOUT 32

__device__ __forceinline__ void mma_h(float* d, const uint32_t* a,
                                      uint32_t b0, uint32_t b1) {
    asm volatile(
        "mma.sync.aligned.m16n8k16.row.col.f32.f16.f16.f32 "
        "{%0,%1,%2,%3}, {%4,%5,%6,%7}, {%8,%9}, {%0,%1,%2,%3};"
        : "+f"(d[0]), "+f"(d[1]), "+f"(d[2]), "+f"(d[3])
        : "r"(a[0]), "r"(a[1]), "r"(a[2]), "r"(a[3]), "r"(b0), "r"(b1));
}
__device__ __forceinline__ void red2(float* p, float x, float y) {
    asm volatile("red.global.add.v2.f32 [%0], {%1, %2};"
                 :: "l"(p), "f"(x), "f"(y) : "memory");
}

// -------------------- scratch (device globals) --------------------
__device__ float g_h[(size_t)N_NODES * DOUT];
__device__ float g_ecomb[B_GRAPH * DOUT];
__device__ float g_ncomb[B_GRAPH * DOUT];
__device__ unsigned int g_ticket;
// fp16 hi-only weight fragments; each uint4 = two n-blocks {b0,b1} pairs
__device__ __align__(16) uint4 gW1frag[6 * 4 * 32];   // edge W1 (k 0..95)
__device__ __align__(16) uint4 gW2frag[4 * 2 * 32];   // edge W2
__device__ __align__(16) uint4 gWn1frag[4 * 4 * 32];  // node W1 (k 0..63)
__device__ __align__(16) uint4 gWn2frag[4 * 2 * 32];  // node W2
// per-graph fused biases: b1 + g_repr[g] @ W1[tail]  (exact fp32 fold)
__device__ __align__(16) float gBias1e[B_GRAPH * HID];
__device__ __align__(16) float gBias1n[B_GRAPH * HID];

__device__ __forceinline__ uint32_t hpack(float a, float b) {
    __half2 h = __floats2half2_rn(a, b);
    return *(uint32_t*)&h;
}

// -------------------- zero + prep --------------------
#define ZERO_BLOCKS 391    // 391*256*4 float4 >= 400k float4 (g_h)
#define PSTRIDE 2048       // 8 prep blocks * 256 threads

__global__ void zero_kernel(const float* __restrict__ W1,
                            const float* __restrict__ W2,
                            const float* __restrict__ Wn1,
                            const float* __restrict__ Wn2,
                            const float* __restrict__ b1e,
                            const float* __restrict__ b1n,
                            const float* __restrict__ g_repr) {
    if (blockIdx.x >= ZERO_BLOCKS) {
        const int pidx = (blockIdx.x - ZERO_BLOCKS) * 256 + threadIdx.x;
        if (pidx == 0) g_ticket = 0;
        if (pidx < 64) ((float4*)g_ecomb)[pidx] = make_float4(0.f, 0.f, 0.f, 0.f);
        else if (pidx < 128) ((float4*)g_ncomb)[pidx - 64] = make_float4(0.f, 0.f, 0.f, 0.f);
        // edge W1 fragments (hi-only fp16), k 0..95
        for (int idx = pidx; idx < 768; idx += PSTRIDE) {
            const int l = idx & 31, p = (idx >> 5) & 3, ks = idx >> 7;
            const int ne = p * 16 + (l >> 2), no = ne + 8;
            const int k0 = ks * 16 + 2 * (l & 3);
            uint4 f;
            f.x = hpack(W1[k0 * 64 + ne], W1[(k0 + 1) * 64 + ne]);
            f.y = hpack(W1[(k0 + 8) * 64 + ne], W1[(k0 + 9) * 64 + ne]);
            f.z = hpack(W1[k0 * 64 + no], W1[(k0 + 1) * 64 + no]);
            f.w = hpack(W1[(k0 + 8) * 64 + no], W1[(k0 + 9) * 64 + no]);
            gW1frag[idx] = f;
        }
        for (int idx = pidx; idx < 256; idx += PSTRIDE) {
            const int l = idx & 31, p = (idx >> 5) & 1, ks2 = idx >> 6;
            const int ne = p * 16 + (l >> 2), no = ne + 8;
            const int k0 = ks2 * 16 + 2 * (l & 3);
            uint4 f;
            f.x = hpack(W2[k0 * 32 + ne], W2[(k0 + 1) * 32 + ne]);
            f.y = hpack(W2[(k0 + 8) * 32 + ne], W2[(k0 + 9) * 32 + ne]);
            f.z = hpack(W2[k0 * 32 + no], W2[(k0 + 1) * 32 + no]);
            f.w = hpack(W2[(k0 + 8) * 32 + no], W2[(k0 + 9) * 32 + no]);
            gW2frag[idx] = f;
        }
        for (int idx = pidx; idx < 512; idx += PSTRIDE) {
            const int l = idx & 31, p = (idx >> 5) & 3, ks = idx >> 7;
            const int ne = p * 16 + (l >> 2), no = ne + 8;
            const int k0 = ks * 16 + 2 * (l & 3);
            uint4 f;
            f.x = hpack(Wn1[k0 * 64 + ne], Wn1[(k0 + 1) * 64 + ne]);
            f.y = hpack(Wn1[(k0 + 8) * 64 + ne], Wn1[(k0 + 9) * 64 + ne]);
            f.z = hpack(Wn1[k0 * 64 + no], Wn1[(k0 + 1) * 64 + no]);
            f.w = hpack(Wn1[(k0 + 8) * 64 + no], Wn1[(k0 + 9) * 64 + no]);
            gWn1frag[idx] = f;
        }
        for (int idx = pidx; idx < 256; idx += PSTRIDE) {
            const int l = idx & 31, p = (idx >> 5) & 1, ks2 = idx >> 6;
            const int ne = p * 16 + (l >> 2), no = ne + 8;
            const int k0 = ks2 * 16 + 2 * (l & 3);
            uint4 f;
            f.x = hpack(Wn2[k0 * 32 + ne], Wn2[(k0 + 1) * 32 + ne]);
            f.y = hpack(Wn2[(k0 + 8) * 32 + ne], Wn2[(k0 + 9) * 32 + ne]);
            f.z = hpack(Wn2[k0 * 32 + no], Wn2[(k0 + 1) * 32 + no]);
            f.w = hpack(Wn2[(k0 + 8) * 32 + no], Wn2[(k0 + 9) * 32 + no]);
            gWn2frag[idx] = f;
        }
        // fused per-graph biases (exact fp32)
        for (int idx = pidx; idx < B_GRAPH * HID; idx += PSTRIDE) {
            const int g = idx >> 6, n = idx & 63;
            float se = b1e[n], sn = b1n[n];
            for (int k = 0; k < 32; k++) {
                se += g_repr[g * 32 + k] * W1[(96 + k) * 64 + n];
                sn += g_repr[g * 32 + k] * Wn1[(64 + k) * 64 + n];
            }
            gBias1e[idx] = se;
            gBias1n[idx] = sn;
        }
        return;
    }
    // g_h zero: 4 float4 per thread (MLP=4)
    size_t base = (size_t)blockIdx.x * 1024 + threadIdx.x;
#pragma unroll
    for (int q = 0; q < 4; q++) {
        size_t i = base + q * 256;
        if (i < (size_t)N_NODES * DOUT / 4)
            ((float4*)g_h)[i] = make_float4(0.f, 0.f, 0.f, 0.f);
    }
}

// float8 -> fp16 hi/lo (X captured to ~2^-22)
__device__ __forceinline__ void cvt8h(float4 a, float4 b, uint4& hi, uint4& lo) {
    __half2 h0 = __floats2half2_rn(a.x, a.y);
    __half2 h1 = __floats2half2_rn(a.z, a.w);
    __half2 h2 = __floats2half2_rn(b.x, b.y);
    __half2 h3 = __floats2half2_rn(b.z, b.w);
    float2 f0 = __half22float2(h0), f1 = __half22float2(h1);
    float2 f2 = __half22float2(h2), f3 = __half22float2(h3);
    __half2 l0 = __floats2half2_rn(a.x - f0.x, a.y - f0.y);
    __half2 l1 = __floats2half2_rn(a.z - f1.x, a.w - f1.y);
    __half2 l2 = __floats2half2_rn(b.x - f2.x, b.y - f2.y);
    __half2 l3 = __floats2half2_rn(b.z - f3.x, b.w - f3.y);
    hi.x = *(uint32_t*)&h0; hi.y = *(uint32_t*)&h1; hi.z = *(uint32_t*)&h2; hi.w = *(uint32_t*)&h3;
    lo.x = *(uint32_t*)&l0; lo.y = *(uint32_t*)&l1; lo.z = *(uint32_t*)&l2; lo.w = *(uint32_t*)&l3;
}

__device__ __forceinline__ void split_frag(float v0, float v1, float v2, float v3,
                                           uint32_t& hA, uint32_t& hB,
                                           uint32_t& lA, uint32_t& lB) {
    __half2 a = __floats2half2_rn(v0, v1);
    __half2 b = __floats2half2_rn(v2, v3);
    float2 fa = __half22float2(a), fb = __half22float2(b);
    __half2 la = __floats2half2_rn(v0 - fa.x, v1 - fa.y);
    __half2 lb = __floats2half2_rn(v2 - fb.x, v3 - fb.y);
    hA = *(uint32_t*)&a; hB = *(uint32_t*)&b;
    lA = *(uint32_t*)&la; lB = *(uint32_t*)&lb;
}

// X tile GEMM pass over stride-72 fp16 hi/lo buffers; 2-term (Xhi+Xlo)*Whi.
template<int KS0, int NKS>
__device__ __forceinline__ void gemm_pass(
    const __half* __restrict__ Xhi, const __half* __restrict__ Xlo,
    const uint4* __restrict__ WF, int r0, int t, int lid, float acc[8][4])
{
#pragma unroll
    for (int ksl = 0; ksl < NKS; ksl++) {
        const int c0 = ksl * 16 + 2 * t;
        const __half* xh = Xhi + r0 * 72 + c0;
        const __half* xl = Xlo + r0 * 72 + c0;
        uint32_t ah[4], al[4];
        ah[0] = *(const uint32_t*)(xh);
        ah[1] = *(const uint32_t*)(xh + 8 * 72);
        ah[2] = *(const uint32_t*)(xh + 8);
        ah[3] = *(const uint32_t*)(xh + 8 * 72 + 8);
        al[0] = *(const uint32_t*)(xl);
        al[1] = *(const uint32_t*)(xl + 8 * 72);
        al[2] = *(const uint32_t*)(xl + 8);
        al[3] = *(const uint32_t*)(xl + 8 * 72 + 8);
        const uint4* wf = WF + ((KS0 + ksl) * 4) * 32 + lid;
#pragma unroll
        for (int p = 0; p < 4; p++) {
            uint4 w = wf[p * 32];
            mma_h(acc[2 * p], ah, w.x, w.y);
            mma_h(acc[2 * p], al, w.x, w.y);
            mma_h(acc[2 * p + 1], ah, w.z, w.w);
            mma_h(acc[2 * p + 1], al, w.z, w.w);
        }
    }
}

// ================== EDGE KERNEL ==================
#define SM_XHI   0        // 128 x 72 fp16 = 18432
#define SM_XLO   18432
#define SM_W1F   36864    // 768 uint4 = 12288
#define SM_BIAS  49152    // 512 f = 2048
#define SM_B2    51200    // 128
#define SM_ES    51328    // 1024
#define SM_TOTAL 52352

__global__ void __launch_bounds__(256, 4) edge_kernel(
    const float* __restrict__ edge_feat, const float* __restrict__ node_feat,
    const int* __restrict__ src, const int* __restrict__ dst,
    const int* __restrict__ e2g, const float* __restrict__ b2,
    float* __restrict__ e_out)
{
    extern __shared__ unsigned char smem[];
    const int tid = threadIdx.x;
    const int wid = tid >> 5, lid = tid & 31;

    __half* Xhi = (__half*)(smem + SM_XHI);
    __half* Xlo = (__half*)(smem + SM_XLO);
    const uint4* W1F = (const uint4*)(smem + SM_W1F);
    float* Bs  = (float*)(smem + SM_BIAS);
    float* b2s = (float*)(smem + SM_B2);
    float* Es  = (float*)(smem + SM_ES);

    {
        uint4* d1 = (uint4*)(smem + SM_W1F);
        for (int i = tid; i < 768; i += 256) d1[i] = gW1frag[i];
        for (int i = tid; i < 512; i += 256) Bs[i] = gBias1e[i];
        if (tid < DOUT) b2s[tid] = b2[tid];
        Es[tid] = 0.f;
    }

    const size_t e0 = (size_t)blockIdx.x * 128;
    const int r = tid >> 1, half = tid & 1;
    const size_t eg = e0 + r;
    const int si = src[eg], di = dst[eg];

    // gather pass 1: k 0..63 = edge_feat || node_feat[src]
    {
        const float4* p = (const float4*)(half ? node_feat + (size_t)si * 32
                                               : edge_feat + eg * 32);
        __half* xh = Xhi + r * 72 + half * 32;
        __half* xl = Xlo + r * 72 + half * 32;
#pragma unroll
        for (int q = 0; q < 4; q++) {
            uint4 hi, lo;
            cvt8h(p[2 * q], p[2 * q + 1], hi, lo);
            *(uint4*)(xh + q * 8) = hi;
            *(uint4*)(xl + q * 8) = lo;
        }
    }
    __syncthreads();

    const int g = lid >> 2, t = lid & 3;
    const int r0 = 16 * wid + g;
    float acc[8][4];
#pragma unroll
    for (int n0 = 0; n0 < 8; n0++)
#pragma unroll
        for (int j = 0; j < 4; j++) acc[n0][j] = 0.f;

    gemm_pass<0, 4>(Xhi, Xlo, W1F, r0, t, lid, acc);
    __syncthreads();

    // gather pass 2: cols 0..31 now hold k 64..95 = node_feat[dst]
    {
        const float4* pd = (const float4*)(node_feat + (size_t)di * 32) + 4 * half;
        __half* xh = Xhi + r * 72 + half * 16;
        __half* xl = Xlo + r * 72 + half * 16;
        uint4 hi, lo;
        cvt8h(pd[0], pd[1], hi, lo);
        *(uint4*)(xh) = hi; *(uint4*)(xl) = lo;
        cvt8h(pd[2], pd[3], hi, lo);
        *(uint4*)(xh + 8) = hi; *(uint4*)(xl + 8) = lo;
    }
    __syncthreads();

    const size_t eA = e0 + r0, eB = eA + 8;
    const int gA = e2g[eA], gB = e2g[eB];

    gemm_pass<4, 2>(Xhi, Xlo, W1F, r0, t, lid, acc);

    // fused bias + relu + register split (fp16 hi/lo A fragments)
    uint32_t Ahi[4][4], Alo[4][4];
#pragma unroll
    for (int n0 = 0; n0 < 8; n0++) {
        const int col = n0 * 8 + 2 * t;
        float2 bbA = *(const float2*)(Bs + gA * 64 + col);
        float2 bbB = *(const float2*)(Bs + gB * 64 + col);
        const int ks2 = n0 >> 1, ib = (n0 & 1) * 2;
        split_frag(fmaxf(acc[n0][0] + bbA.x, 0.f), fmaxf(acc[n0][1] + bbA.y, 0.f),
                   fmaxf(acc[n0][2] + bbB.x, 0.f), fmaxf(acc[n0][3] + bbB.y, 0.f),
                   Ahi[ks2][ib], Ahi[ks2][ib + 1], Alo[ks2][ib], Alo[ks2][ib + 1]);
    }

    // GEMM2: K=64, 2-term, weight fragments from L1/L2
    float d2[4][4];
#pragma unroll
    for (int nb = 0; nb < 4; nb++)
#pragma unroll
        for (int j = 0; j < 4; j++) d2[nb][j] = 0.f;

#pragma unroll
    for (int ks2 = 0; ks2 < 4; ks2++) {
        const uint4* wf = gW2frag + (ks2 * 2) * 32 + lid;
#pragma unroll
        for (int p = 0; p < 2; p++) {
            uint4 w = wf[p * 32];
            mma_h(d2[2 * p], Ahi[ks2], w.x, w.y);
            mma_h(d2[2 * p], Alo[ks2], w.x, w.y);
            mma_h(d2[2 * p + 1], Ahi[ks2], w.z, w.w);
            mma_h(d2[2 * p + 1], Alo[ks2], w.z, w.w);
        }
    }

    // epilogue (per-nb, register-lean)
    {
        const int dA = dst[eA], dB = dst[eB];
        const bool uni = (e2g[e0 + 16 * wid] == e2g[e0 + 16 * wid + 15]);
        float* hA = g_h + (size_t)dA * 32;
        float* hB = g_h + (size_t)dB * 32;
        float* oA = e_out + eA * 32;
        float* oB = e_out + eB * 32;
#pragma unroll
        for (int nb = 0; nb < 4; nb++) {
            const int col = nb * 8 + 2 * t;
            float2 bb = *(const float2*)(b2s + col);
            float a0 = d2[nb][0] + bb.x, a1 = d2[nb][1] + bb.y;
            float c0 = d2[nb][2] + bb.x, c1 = d2[nb][3] + bb.y;
            *(float2*)(oA + col) = make_float2(a0, a1);
            *(float2*)(oB + col) = make_float2(c0, c1);
            red2(hA + col, a0, a1);
            red2(hB + col, c0, c1);
            if (uni) {
                float s0 = a0 + c0, s1 = a1 + c1;
#pragma unroll
                for (int m = 4; m <= 16; m <<= 1) {
                    s0 += __shfl_xor_sync(0xFFFFFFFFu, s0, m);
                    s1 += __shfl_xor_sync(0xFFFFFFFFu, s1, m);
                }
                if (g == 0) {
                    atomicAdd(&Es[gA * 32 + col], s0);
                    atomicAdd(&Es[gA * 32 + col + 1], s1);
                }
            } else {
                atomicAdd(&Es[gA * 32 + col], a0);
                atomicAdd(&Es[gA * 32 + col + 1], a1);
                atomicAdd(&Es[gB * 32 + col], c0);
                atomicAdd(&Es[gB * 32 + col + 1], c1);
            }
        }
    }
    __syncthreads();
    atomicAdd(&g_ecomb[tid], Es[tid]);
}

// ================== NODE KERNEL + global tail ==================
#define NSM_XHI   0        // 128 x 72 fp16 = 18432
#define NSM_XLO   18432
#define NSM_W1F   36864    // 512 uint4 = 8192
#define NSM_BIAS  45056    // 2048
#define NSM_B2    47104    // 128
#define NSM_NS    47232    // 1024
#define NSM_TOTAL 48256

__global__ void __launch_bounds__(256, 4) node_kernel(
    const float* __restrict__ node_feat, const float* __restrict__ g_repr,
    const int* __restrict__ n2g, const float* __restrict__ b2,
    const float* __restrict__ Wu1, const float* __restrict__ bu1,
    const float* __restrict__ Wu2, const float* __restrict__ bu2,
    float* __restrict__ n_out, float* __restrict__ g_out)
{
    extern __shared__ unsigned char smem[];
    const int tid = threadIdx.x;
    const int wid = tid >> 5, lid = tid & 31;

    __half* Xhi = (__half*)(smem + NSM_XHI);
    __half* Xlo = (__half*)(smem + NSM_XLO);
    const uint4* W1F = (const uint4*)(smem + NSM_W1F);
    float* Bs  = (float*)(smem + NSM_BIAS);
    float* b2s = (float*)(smem + NSM_B2);
    float* Ns  = (float*)(smem + NSM_NS);

    {
        uint4* d1 = (uint4*)(smem + NSM_W1F);
        for (int i = tid; i < 512; i += 256) d1[i] = gWn1frag[i];
        for (int i = tid; i < 512; i += 256) Bs[i] = gBias1n[i];
        if (tid < DOUT) b2s[tid] = b2[tid];
        Ns[tid] = 0.f;
    }

    const int n0base = blockIdx.x * 128;

    // gather: k 0..63 = node_feat || g_h
    {
        const int r = tid >> 1, half = tid & 1;
        const int node = n0base + r;
        __half* xh = Xhi + r * 72 + half * 32;
        __half* xl = Xlo + r * 72 + half * 32;
        if (node < N_NODES) {
            const float4* p = (const float4*)((half ? g_h : node_feat) + (size_t)node * 32);
#pragma unroll
            for (int q = 0; q < 4; q++) {
                uint4 hi, lo;
                cvt8h(p[2 * q], p[2 * q + 1], hi, lo);
                *(uint4*)(xh + q * 8) = hi;
                *(uint4*)(xl + q * 8) = lo;
            }
        } else {
            const uint4 z = make_uint4(0, 0, 0, 0);
#pragma unroll
            for (int q = 0; q < 4; q++) {
                *(uint4*)(xh + q * 8) = z;
                *(uint4*)(xl + q * 8) = z;
            }
        }
    }
    __syncthreads();

    const int g = lid >> 2, t = lid & 3;
    const int r0 = 16 * wid + g;
    float acc[8][4];
#pragma unroll
    for (int n0 = 0; n0 < 8; n0++)
#pragma unroll
        for (int j = 0; j < 4; j++) acc[n0][j] = 0.f;

    gemm_pass<0, 4>(Xhi, Xlo, W1F, r0, t, lid, acc);

    const int nA = n0base + r0, nB = nA + 8;
    const bool vA = nA < N_NODES, vB = nB < N_NODES;
    const int gA = vA ? n2g[nA] : 0, gB = vB ? n2g[nB] : 0;

    uint32_t Ahi[4][4], Alo[4][4];
#pragma unroll
    for (int n0 = 0; n0 < 8; n0++) {
        const int col = n0 * 8 + 2 * t;
        float2 bbA = *(const float2*)(Bs + gA * 64 + col);
        float2 bbB = *(const float2*)(Bs + gB * 64 + col);
        const int ks2 = n0 >> 1, ib = (n0 & 1) * 2;
        split_frag(fmaxf(acc[n0][0] + bbA.x, 0.f), fmaxf(acc[n0][1] + bbA.y, 0.f),
                   fmaxf(acc[n0][2] + bbB.x, 0.f), fmaxf(acc[n0][3] + bbB.y, 0.f),
                   Ahi[ks2][ib], Ahi[ks2][ib + 1], Alo[ks2][ib], Alo[ks2][ib + 1]);
    }

    float d2[4][4];
#pragma unroll
    for (int nb = 0; nb < 4; nb++)
#pragma unroll
        for (int j = 0; j < 4; j++) d2[nb][j] = 0.f;

#pragma unroll
    for (int ks2 = 0; ks2 < 4; ks2++) {
        const uint4* wf = gWn2frag + (ks2 * 2) * 32 + lid;
#pragma unroll
        for (int p = 0; p < 2; p++) {
            uint4 w = wf[p * 32];
            mma_h(d2[2 * p], Ahi[ks2], w.x, w.y);
            mma_h(d2[2 * p], Alo[ks2], w.x, w.y);
            mma_h(d2[2 * p + 1], Ahi[ks2], w.z, w.w);
            mma_h(d2[2 * p + 1], Alo[ks2], w.z, w.w);
        }
    }

    // epilogue (per-nb)
    {
        const bool warpFull = (n0base + 16 * wid + 15) < N_NODES;
        const bool uni = warpFull &&
            (n2g[n0base + 16 * wid] == n2g[n0base + 16 * wid + 15]);
#pragma unroll
        for (int nb = 0; nb < 4; nb++) {
            const int col = nb * 8 + 2 * t;
            float2 bb = *(const float2*)(b2s + col);
            float a0 = d2[nb][0] + bb.x, a1 = d2[nb][1] + bb.y;
            float c0 = d2[nb][2] + bb.x, c1 = d2[nb][3] + bb.y;
            if (vA) *(float2*)(n_out + (size_t)nA * 32 + col) = make_float2(a0, a1);
            if (vB) *(float2*)(n_out + (size_t)nB * 32 + col) = make_float2(c0, c1);
            if (uni) {
                float s0 = a0 + c0, s1 = a1 + c1;
#pragma unroll
                for (int m = 4; m <= 16; m <<= 1) {
                    s0 += __shfl_xor_sync(0xFFFFFFFFu, s0, m);
                    s1 += __shfl_xor_sync(0xFFFFFFFFu, s1, m);
                }
                if (g == 0) {
                    atomicAdd(&Ns[gA * 32 + col], s0);
                    atomicAdd(&Ns[gA * 32 + col + 1], s1);
                }
            } else {
                if (vA) {
                    atomicAdd(&Ns[gA * 32 + col], a0);
                    atomicAdd(&Ns[gA * 32 + col + 1], a1);
                }
                if (vB) {
                    atomicAdd(&Ns[gB * 32 + col], c0);
                    atomicAdd(&Ns[gB * 32 + col + 1], c1);
                }
            }
        }
    }
    __syncthreads();
    atomicAdd(&g_ncomb[tid], Ns[tid]);

    // -------- last-block global MLP tail --------
    __shared__ unsigned s_done;
    __threadfence();
    __syncthreads();
    if (tid == 0) {
        unsigned tk = atomicAdd(&g_ticket, 1);
        s_done = (tk == gridDim.x - 1) ? 1u : 0u;
    }
    __syncthreads();
    if (!s_done) return;
    __threadfence();

    float* U   = (float*)(smem + 0);        // 768 f
    float* W1u = (float*)(smem + 4096);     // 6144 f
    float* W2u = (float*)(smem + 28672);    // 2048 f
    float* Hg  = (float*)(smem + 40960);    // 512 f

    for (int i = tid; i < B_GRAPH * 96; i += 256) {
        const int b = i / 96, c = i % 96;
        float v;
        if (c < 32)      v = g_ncomb[b * 32 + c];
        else if (c < 64) v = g_ecomb[b * 32 + (c - 32)];
        else             v = g_repr[b * 32 + (c - 64)];
        U[i] = v;
    }
    {
        const float4* wg = (const float4*)Wu1; float4* ws = (float4*)W1u;
        for (int i = tid; i < 1536; i += 256) ws[i] = wg[i];
        const float4* w2g = (const float4*)Wu2; float4* w2s = (float4*)W2u;
        for (int i = tid; i < 512; i += 256) w2s[i] = w2g[i];
    }
    __syncthreads();

    for (int idx = tid; idx < B_GRAPH * HID; idx += 256) {
        const int b = idx >> 6, j = idx & 63;
        float s = bu1[j];
#pragma unroll 8
        for (int k = 0; k < 96; k++) s += U[b * 96 + k] * W1u[k * 64 + j];
        Hg[idx] = fmaxf(s, 0.f);
    }
    __syncthreads();
    for (int idx = tid; idx < B_GRAPH * DOUT; idx += 256) {
        const int b = idx >> 5, c = idx & 31;
        float s = bu2[c];
#pragma unroll 8
        for (int k = 0; k < 64; k++) s += Hg[b * 64 + k] * W2u[k * 32 + c];
        g_out[idx] = s;
    }
}

extern "C" void kernel_launch(void* const* d_in, const int* in_sizes, int n_in,
                              void* d_out, int out_size)
{
    const float* edge_feat = (const float*)d_in[0];
    const float* node_feat = (const float*)d_in[1];
    const float* g_repr    = (const float*)d_in[2];
    const int*   src       = (const int*)d_in[3];
    const int*   dst       = (const int*)d_in[4];
    const int*   n2g       = (const int*)d_in[5];
    const int*   e2g       = (const int*)d_in[6];
    const float* W_e1 = (const float*)d_in[7];
    const float* b_e1 = (const float*)d_in[8];
    const float* W_e2 = (const float*)d_in[9];
    const float* b_e2 = (const float*)d_in[10];
    const float* W_n1 = (const float*)d_in[11];
    const float* b_n1 = (const float*)d_in[12];
    const float* W_n2 = (const float*)d_in[13];
    const float* b_n2 = (const float*)d_in[14];
    const float* W_u1 = (const float*)d_in[15];
    const float* b_u1 = (const float*)d_in[16];
    const float* W_u2 = (const float*)d_in[17];
    const float* b_u2 = (const float*)d_in[18];

    float* out = (float*)d_out;
    float* e_out = out;                                      // [E, 32]
    float* n_out = out + (size_t)N_EDGES * DOUT;             // [N, 32]
    float* g_out = out + (size_t)(N_EDGES + N_NODES) * DOUT; // [B, 32]

    cudaFuncSetAttribute(edge_kernel, cudaFuncAttributeMaxDynamicSharedMemorySize, SM_TOTAL);
    cudaFuncSetAttribute(node_kernel, cudaFuncAttributeMaxDynamicSharedMemorySize, NSM_TOTAL);

    zero_kernel<<<ZERO_BLOCKS + 8, 256>>>(W_e1, W_e2, W_n1, W_n2,
                                          b_e1, b_n1, g_repr);
    edge_kernel<<<N_EDGES / 128, 256, SM_TOTAL>>>(
        edge_feat, node_feat, src, dst, e2g, b_e2, e_out);
    node_kernel<<<(N_NODES + 127) / 128, 256, NSM_TOTAL>>>(
        node_feat, g_repr, n2g, b_n2,
        W_u1, b_u1, W_u2, b_u2, n_out, g_out);
}

// round 12
// speedup vs baseline: 1.0447x; 1.0447x over previous
#include <cuda_runtime.h>
#include <cuda_fp16.h>
#include <cstdint>

#define N_NODES 50000
#define N_EDGES 800000
#define B_GRAPH 8
#define HID 64
#define DOUT 32

__device__ __forceinline__ void mma_h(float* d, const uint32_t* a,
                                      uint32_t b0, uint32_t b1) {
    asm volatile(
        "mma.sync.aligned.m16n8k16.row.col.f32.f16.f16.f32 "
        "{%0,%1,%2,%3}, {%4,%5,%6,%7}, {%8,%9}, {%0,%1,%2,%3};"
        : "+f"(d[0]), "+f"(d[1]), "+f"(d[2]), "+f"(d[3])
        : "r"(a[0]), "r"(a[1]), "r"(a[2]), "r"(a[3]), "r"(b0), "r"(b1));
}
__device__ __forceinline__ void red2(float* p, float x, float y) {
    asm volatile("red.global.add.v2.f32 [%0], {%1, %2};"
                 :: "l"(p), "f"(x), "f"(y) : "memory");
}

// -------------------- scratch (device globals) --------------------
__device__ float g_h[(size_t)N_NODES * DOUT];
__device__ float g_ecomb[B_GRAPH * DOUT];
__device__ float g_ncomb[B_GRAPH * DOUT];
__device__ unsigned int g_ticket;
// fp16 hi-only weight fragments; each uint4 = two n-blocks {b0,b1} pairs
__device__ __align__(16) uint4 gW1frag[6 * 4 * 32];   // edge W1 (k 0..95)
__device__ __align__(16) uint4 gW2frag[4 * 2 * 32];   // edge W2
__device__ __align__(16) uint4 gWn1frag[4 * 4 * 32];  // node W1 (k 0..63)
__device__ __align__(16) uint4 gWn2frag[4 * 2 * 32];  // node W2
// per-graph fused biases: b1 + g_repr[g] @ W1[tail]  (exact fp32 fold)
__device__ __align__(16) float gBias1e[B_GRAPH * HID];
__device__ __align__(16) float gBias1n[B_GRAPH * HID];

__device__ __forceinline__ uint32_t hpack(float a, float b) {
    __half2 h = __floats2half2_rn(a, b);
    return *(uint32_t*)&h;
}

// -------------------- zero + prep --------------------
#define ZERO_BLOCKS 391    // 391*256*4 float4 >= 400k float4 (g_h)
#define PSTRIDE 2048       // 8 prep blocks * 256 threads

__global__ void zero_kernel(const float* __restrict__ W1,
                            const float* __restrict__ W2,
                            const float* __restrict__ Wn1,
                            const float* __restrict__ Wn2,
                            const float* __restrict__ b1e,
                            const float* __restrict__ b1n,
                            const float* __restrict__ g_repr) {
    if (blockIdx.x >= ZERO_BLOCKS) {
        const int pidx = (blockIdx.x - ZERO_BLOCKS) * 256 + threadIdx.x;
        if (pidx == 0) g_ticket = 0;
        if (pidx < 64) ((float4*)g_ecomb)[pidx] = make_float4(0.f, 0.f, 0.f, 0.f);
        else if (pidx < 128) ((float4*)g_ncomb)[pidx - 64] = make_float4(0.f, 0.f, 0.f, 0.f);
        // edge W1 fragments (hi-only fp16), k 0..95
        for (int idx = pidx; idx < 768; idx += PSTRIDE) {
            const int l = idx & 31, p = (idx >> 5) & 3, ks = idx >> 7;
            const int ne = p * 16 + (l >> 2), no = ne + 8;
            const int k0 = ks * 16 + 2 * (l & 3);
            uint4 f;
            f.x = hpack(W1[k0 * 64 + ne], W1[(k0 + 1) * 64 + ne]);
            f.y = hpack(W1[(k0 + 8) * 64 + ne], W1[(k0 + 9) * 64 + ne]);
            f.z = hpack(W1[k0 * 64 + no], W1[(k0 + 1) * 64 + no]);
            f.w = hpack(W1[(k0 + 8) * 64 + no], W1[(k0 + 9) * 64 + no]);
            gW1frag[idx] = f;
        }
        for (int idx = pidx; idx < 256; idx += PSTRIDE) {
            const int l = idx & 31, p = (idx >> 5) & 1, ks2 = idx >> 6;
            const int ne = p * 16 + (l >> 2), no = ne + 8;
            const int k0 = ks2 * 16 + 2 * (l & 3);
            uint4 f;
            f.x = hpack(W2[k0 * 32 + ne], W2[(k0 + 1) * 32 + ne]);
            f.y = hpack(W2[(k0 + 8) * 32 + ne], W2[(k0 + 9) * 32 + ne]);
            f.z = hpack(W2[k0 * 32 + no], W2[(k0 + 1) * 32 + no]);
            f.w = hpack(W2[(k0 + 8) * 32 + no], W2[(k0 + 9) * 32 + no]);
            gW2frag[idx] = f;
        }
        for (int idx = pidx; idx < 512; idx += PSTRIDE) {
            const int l = idx & 31, p = (idx >> 5) & 3, ks = idx >> 7;
            const int ne = p * 16 + (l >> 2), no = ne + 8;
            const int k0 = ks * 16 + 2 * (l & 3);
            uint4 f;
            f.x = hpack(Wn1[k0 * 64 + ne], Wn1[(k0 + 1) * 64 + ne]);
            f.y = hpack(Wn1[(k0 + 8) * 64 + ne], Wn1[(k0 + 9) * 64 + ne]);
            f.z = hpack(Wn1[k0 * 64 + no], Wn1[(k0 + 1) * 64 + no]);
            f.w = hpack(Wn1[(k0 + 8) * 64 + no], Wn1[(k0 + 9) * 64 + no]);
            gWn1frag[idx] = f;
        }
        for (int idx = pidx; idx < 256; idx += PSTRIDE) {
            const int l = idx & 31, p = (idx >> 5) & 1, ks2 = idx >> 6;
            const int ne = p * 16 + (l >> 2), no = ne + 8;
            const int k0 = ks2 * 16 + 2 * (l & 3);
            uint4 f;
            f.x = hpack(Wn2[k0 * 32 + ne], Wn2[(k0 + 1) * 32 + ne]);
            f.y = hpack(Wn2[(k0 + 8) * 32 + ne], Wn2[(k0 + 9) * 32 + ne]);
            f.z = hpack(Wn2[k0 * 32 + no], Wn2[(k0 + 1) * 32 + no]);
            f.w = hpack(Wn2[(k0 + 8) * 32 + no], Wn2[(k0 + 9) * 32 + no]);
            gWn2frag[idx] = f;
        }
        // fused per-graph biases (exact fp32)
        for (int idx = pidx; idx < B_GRAPH * HID; idx += PSTRIDE) {
            const int g = idx >> 6, n = idx & 63;
            float se = b1e[n], sn = b1n[n];
            for (int k = 0; k < 32; k++) {
                se += g_repr[g * 32 + k] * W1[(96 + k) * 64 + n];
                sn += g_repr[g * 32 + k] * Wn1[(64 + k) * 64 + n];
            }
            gBias1e[idx] = se;
            gBias1n[idx] = sn;
        }
        return;
    }
    // g_h zero: 4 float4 per thread (MLP=4)
    size_t base = (size_t)blockIdx.x * 1024 + threadIdx.x;
#pragma unroll
    for (int q = 0; q < 4; q++) {
        size_t i = base + q * 256;
        if (i < (size_t)N_NODES * DOUT / 4)
            ((float4*)g_h)[i] = make_float4(0.f, 0.f, 0.f, 0.f);
    }
}

// float8 -> fp16 hi/lo (X captured to ~2^-22)
__device__ __forceinline__ void cvt8h(float4 a, float4 b, uint4& hi, uint4& lo) {
    __half2 h0 = __floats2half2_rn(a.x, a.y);
    __half2 h1 = __floats2half2_rn(a.z, a.w);
    __half2 h2 = __floats2half2_rn(b.x, b.y);
    __half2 h3 = __floats2half2_rn(b.z, b.w);
    float2 f0 = __half22float2(h0), f1 = __half22float2(h1);
    float2 f2 = __half22float2(h2), f3 = __half22float2(h3);
    __half2 l0 = __floats2half2_rn(a.x - f0.x, a.y - f0.y);
    __half2 l1 = __floats2half2_rn(a.z - f1.x, a.w - f1.y);
    __half2 l2 = __floats2half2_rn(b.x - f2.x, b.y - f2.y);
    __half2 l3 = __floats2half2_rn(b.z - f3.x, b.w - f3.y);
    hi.x = *(uint32_t*)&h0; hi.y = *(uint32_t*)&h1; hi.z = *(uint32_t*)&h2; hi.w = *(uint32_t*)&h3;
    lo.x = *(uint32_t*)&l0; lo.y = *(uint32_t*)&l1; lo.z = *(uint32_t*)&l2; lo.w = *(uint32_t*)&l3;
}

__device__ __forceinline__ void split_frag(float v0, float v1, float v2, float v3,
                                           uint32_t& hA, uint32_t& hB,
                                           uint32_t& lA, uint32_t& lB) {
    __half2 a = __floats2half2_rn(v0, v1);
    __half2 b = __floats2half2_rn(v2, v3);
    float2 fa = __half22float2(a), fb = __half22float2(b);
    __half2 la = __floats2half2_rn(v0 - fa.x, v1 - fa.y);
    __half2 lb = __floats2half2_rn(v2 - fb.x, v3 - fb.y);
    hA = *(uint32_t*)&a; hB = *(uint32_t*)&b;
    lA = *(uint32_t*)&la; lB = *(uint32_t*)&lb;
}

// X tile GEMM pass; STRIDE in halves. 2-term (Xhi+Xlo)*Whi.
template<int KS0, int NKS, int STRIDE>
__device__ __forceinline__ void gemm_pass(
    const __half* __restrict__ Xhi, const __half* __restrict__ Xlo,
    const uint4* __restrict__ WF, int r0, int t, int lid, float acc[8][4])
{
#pragma unroll
    for (int ksl = 0; ksl < NKS; ksl++) {
        const int c0 = ksl * 16 + 2 * t;
        const __half* xh = Xhi + r0 * STRIDE + c0;
        const __half* xl = Xlo + r0 * STRIDE + c0;
        uint32_t ah[4], al[4];
        ah[0] = *(const uint32_t*)(xh);
        ah[1] = *(const uint32_t*)(xh + 8 * STRIDE);
        ah[2] = *(const uint32_t*)(xh + 8);
        ah[3] = *(const uint32_t*)(xh + 8 * STRIDE + 8);
        al[0] = *(const uint32_t*)(xl);
        al[1] = *(const uint32_t*)(xl + 8 * STRIDE);
        al[2] = *(const uint32_t*)(xl + 8);
        al[3] = *(const uint32_t*)(xl + 8 * STRIDE + 8);
        const uint4* wf = WF + ((KS0 + ksl) * 4) * 32 + lid;
#pragma unroll
        for (int p = 0; p < 4; p++) {
            uint4 w = wf[p * 32];
            mma_h(acc[2 * p], ah, w.x, w.y);
            mma_h(acc[2 * p], al, w.x, w.y);
            mma_h(acc[2 * p + 1], ah, w.z, w.w);
            mma_h(acc[2 * p + 1], al, w.z, w.w);
        }
    }
}

// ================== EDGE KERNEL (single-phase gather, stride 104) ==================
#define SM_XHI   0        // 128 x 104 fp16 = 26624
#define SM_XLO   26624
#define SM_W1F   53248    // 768 uint4 = 12288
#define SM_BIAS  65536    // 512 f = 2048
#define SM_B2    67584    // 128
#define SM_ES    67712    // 1024
#define SM_TOTAL 68736

__global__ void __launch_bounds__(256, 3) edge_kernel(
    const float* __restrict__ edge_feat, const float* __restrict__ node_feat,
    const int* __restrict__ src, const int* __restrict__ dst,
    const int* __restrict__ e2g, const float* __restrict__ b2,
    float* __restrict__ e_out)
{
    extern __shared__ unsigned char smem[];
    const int tid = threadIdx.x;
    const int wid = tid >> 5, lid = tid & 31;

    __half* Xhi = (__half*)(smem + SM_XHI);
    __half* Xlo = (__half*)(smem + SM_XLO);
    const uint4* W1F = (const uint4*)(smem + SM_W1F);
    float* Bs  = (float*)(smem + SM_BIAS);
    float* b2s = (float*)(smem + SM_B2);
    float* Es  = (float*)(smem + SM_ES);

    {
        uint4* d1 = (uint4*)(smem + SM_W1F);
        for (int i = tid; i < 768; i += 256) d1[i] = gW1frag[i];
        for (int i = tid; i < 512; i += 256) Bs[i] = gBias1e[i];
        if (tid < DOUT) b2s[tid] = b2[tid];
        Es[tid] = 0.f;
    }

    const size_t e0 = (size_t)blockIdx.x * 128;
    const int r = tid >> 1, half = tid & 1;
    const size_t eg = e0 + r;

    // single gather phase: all 96 cols = edge_feat || node_feat[src] || node_feat[dst]
    // half 0 -> cols 0..47, half 1 -> cols 48..95; all LDGs issued together.
    {
        __half* xh = Xhi + r * 104 + half * 48;
        __half* xl = Xlo + r * 104 + half * 48;
        if (half == 0) {
            const float4* pe = (const float4*)(edge_feat + eg * 32);
            const float4* ps = (const float4*)(node_feat + (size_t)src[eg] * 32);
            float4 v0 = pe[0], v1 = pe[1], v2 = pe[2], v3 = pe[3];
            float4 v4 = pe[4], v5 = pe[5], v6 = pe[6], v7 = pe[7];
            float4 s0 = ps[0], s1 = ps[1], s2 = ps[2], s3 = ps[3];
            uint4 hi, lo;
            cvt8h(v0, v1, hi, lo); *(uint4*)(xh) = hi;      *(uint4*)(xl) = lo;
            cvt8h(v2, v3, hi, lo); *(uint4*)(xh + 8) = hi;  *(uint4*)(xl + 8) = lo;
            cvt8h(v4, v5, hi, lo); *(uint4*)(xh + 16) = hi; *(uint4*)(xl + 16) = lo;
            cvt8h(v6, v7, hi, lo); *(uint4*)(xh + 24) = hi; *(uint4*)(xl + 24) = lo;
            cvt8h(s0, s1, hi, lo); *(uint4*)(xh + 32) = hi; *(uint4*)(xl + 32) = lo;
            cvt8h(s2, s3, hi, lo); *(uint4*)(xh + 40) = hi; *(uint4*)(xl + 40) = lo;
        } else {
            const float4* ps = (const float4*)(node_feat + (size_t)src[eg] * 32) + 4;
            const float4* pd = (const float4*)(node_feat + (size_t)dst[eg] * 32);
            float4 s0 = ps[0], s1 = ps[1], s2 = ps[2], s3 = ps[3];
            float4 d0 = pd[0], d1 = pd[1], d2v = pd[2], d3 = pd[3];
            float4 d4 = pd[4], d5 = pd[5], d6 = pd[6], d7 = pd[7];
            uint4 hi, lo;
            cvt8h(s0, s1, hi, lo);  *(uint4*)(xh) = hi;      *(uint4*)(xl) = lo;
            cvt8h(s2, s3, hi, lo);  *(uint4*)(xh + 8) = hi;  *(uint4*)(xl + 8) = lo;
            cvt8h(d0, d1, hi, lo);  *(uint4*)(xh + 16) = hi; *(uint4*)(xl + 16) = lo;
            cvt8h(d2v, d3, hi, lo); *(uint4*)(xh + 24) = hi; *(uint4*)(xl + 24) = lo;
            cvt8h(d4, d5, hi, lo);  *(uint4*)(xh + 32) = hi; *(uint4*)(xl + 32) = lo;
            cvt8h(d6, d7, hi, lo);  *(uint4*)(xh + 40) = hi; *(uint4*)(xl + 40) = lo;
        }
    }
    __syncthreads();

    const int g = lid >> 2, t = lid & 3;
    const int r0 = 16 * wid + g;
    float acc[8][4];
#pragma unroll
    for (int n0 = 0; n0 < 8; n0++)
#pragma unroll
        for (int j = 0; j < 4; j++) acc[n0][j] = 0.f;

    gemm_pass<0, 6, 104>(Xhi, Xlo, W1F, r0, t, lid, acc);

    const size_t eA = e0 + r0, eB = eA + 8;
    const int gA = e2g[eA], gB = e2g[eB];

    // fused bias + relu + register split (fp16 hi/lo A fragments)
    uint32_t Ahi[4][4], Alo[4][4];
#pragma unroll
    for (int n0 = 0; n0 < 8; n0++) {
        const int col = n0 * 8 + 2 * t;
        float2 bbA = *(const float2*)(Bs + gA * 64 + col);
        float2 bbB = *(const float2*)(Bs + gB * 64 + col);
        const int ks2 = n0 >> 1, ib = (n0 & 1) * 2;
        split_frag(fmaxf(acc[n0][0] + bbA.x, 0.f), fmaxf(acc[n0][1] + bbA.y, 0.f),
                   fmaxf(acc[n0][2] + bbB.x, 0.f), fmaxf(acc[n0][3] + bbB.y, 0.f),
                   Ahi[ks2][ib], Ahi[ks2][ib + 1], Alo[ks2][ib], Alo[ks2][ib + 1]);
    }

    // GEMM2: K=64, 2-term, weight fragments from L1/L2
    float d2[4][4];
#pragma unroll
    for (int nb = 0; nb < 4; nb++)
#pragma unroll
        for (int j = 0; j < 4; j++) d2[nb][j] = 0.f;

#pragma unroll
    for (int ks2 = 0; ks2 < 4; ks2++) {
        const uint4* wf = gW2frag + (ks2 * 2) * 32 + lid;
#pragma unroll
        for (int p = 0; p < 2; p++) {
            uint4 w = wf[p * 32];
            mma_h(d2[2 * p], Ahi[ks2], w.x, w.y);
            mma_h(d2[2 * p], Alo[ks2], w.x, w.y);
            mma_h(d2[2 * p + 1], Ahi[ks2], w.z, w.w);
            mma_h(d2[2 * p + 1], Alo[ks2], w.z, w.w);
        }
    }

    // epilogue (R9 layout)
    {
        const int dA = dst[eA], dB = dst[eB];
        const int gFirst = e2g[e0 + 16 * wid];
        const int gLast  = e2g[e0 + 16 * wid + 15];
        float* hA = g_h + (size_t)dA * 32;
        float* hB = g_h + (size_t)dB * 32;
        float* oA = e_out + eA * 32;
        float* oB = e_out + eB * 32;
        float a0[4], a1[4], c0v[4], c1[4];
#pragma unroll
        for (int nb = 0; nb < 4; nb++) {
            const int col = nb * 8 + 2 * t;
            float2 bb = *(const float2*)(b2s + col);
            a0[nb] = d2[nb][0] + bb.x;  a1[nb] = d2[nb][1] + bb.y;
            c0v[nb] = d2[nb][2] + bb.x; c1[nb] = d2[nb][3] + bb.y;
            *(float2*)(oA + col) = make_float2(a0[nb], a1[nb]);
            *(float2*)(oB + col) = make_float2(c0v[nb], c1[nb]);
            red2(hA + col, a0[nb], a1[nb]);
            red2(hB + col, c0v[nb], c1[nb]);
        }
        if (gFirst == gLast) {
#pragma unroll
            for (int nb = 0; nb < 4; nb++) {
                float s0 = a0[nb] + c0v[nb];
                float s1 = a1[nb] + c1[nb];
#pragma unroll
                for (int m = 4; m <= 16; m <<= 1) {
                    s0 += __shfl_xor_sync(0xFFFFFFFFu, s0, m);
                    s1 += __shfl_xor_sync(0xFFFFFFFFu, s1, m);
                }
                if (g == 0) {
                    const int col = nb * 8 + 2 * t;
                    atomicAdd(&Es[gFirst * 32 + col], s0);
                    atomicAdd(&Es[gFirst * 32 + col + 1], s1);
                }
            }
        } else {
#pragma unroll
            for (int nb = 0; nb < 4; nb++) {
                const int col = nb * 8 + 2 * t;
                atomicAdd(&Es[gA * 32 + col], a0[nb]);
                atomicAdd(&Es[gA * 32 + col + 1], a1[nb]);
                atomicAdd(&Es[gB * 32 + col], c0v[nb]);
                atomicAdd(&Es[gB * 32 + col + 1], c1[nb]);
            }
        }
    }
    __syncthreads();
    atomicAdd(&g_ecomb[tid], Es[tid]);
}

// ================== NODE KERNEL + global tail (R9 verbatim) ==================
#define NSM_XHI   0        // 128 x 72 fp16 = 18432
#define NSM_XLO   18432
#define NSM_W1F   36864    // 512 uint4 = 8192
#define NSM_BIAS  45056    // 2048
#define NSM_B2    47104    // 128
#define NSM_NS    47232    // 1024
#define NSM_TOTAL 48256

__global__ void __launch_bounds__(256, 3) node_kernel(
    const float* __restrict__ node_feat, const float* __restrict__ g_repr,
    const int* __restrict__ n2g, const float* __restrict__ b2,
    const float* __restrict__ Wu1, const float* __restrict__ bu1,
    const float* __restrict__ Wu2, const float* __restrict__ bu2,
    float* __restrict__ n_out, float* __restrict__ g_out)
{
    extern __shared__ unsigned char smem[];
    const int tid = threadIdx.x;
    const int wid = tid >> 5, lid = tid & 31;

    __half* Xhi = (__half*)(smem + NSM_XHI);
    __half* Xlo = (__half*)(smem + NSM_XLO);
    const uint4* W1F = (const uint4*)(smem + NSM_W1F);
    float* Bs  = (float*)(smem + NSM_BIAS);
    float* b2s = (float*)(smem + NSM_B2);
    float* Ns  = (float*)(smem + NSM_NS);

    {
        uint4* d1 = (uint4*)(smem + NSM_W1F);
        for (int i = tid; i < 512; i += 256) d1[i] = gWn1frag[i];
        for (int i = tid; i < 512; i += 256) Bs[i] = gBias1n[i];
        if (tid < DOUT) b2s[tid] = b2[tid];
        Ns[tid] = 0.f;
    }

    const int n0base = blockIdx.x * 128;

    // gather: k 0..63 = node_feat || g_h
    {
        const int r = tid >> 1, half = tid & 1;
        const int node = n0base + r;
        __half* xh = Xhi + r * 72 + half * 32;
        __half* xl = Xlo + r * 72 + half * 32;
        if (node < N_NODES) {
            const float4* p = (const float4*)((half ? g_h : node_feat) + (size_t)node * 32);
#pragma unroll
            for (int q = 0; q < 4; q++) {
                uint4 hi, lo;
                cvt8h(p[2 * q], p[2 * q + 1], hi, lo);
                *(uint4*)(xh + q * 8) = hi;
                *(uint4*)(xl + q * 8) = lo;
            }
        } else {
            const uint4 z = make_uint4(0, 0, 0, 0);
#pragma unroll
            for (int q = 0; q < 4; q++) {
                *(uint4*)(xh + q * 8) = z;
                *(uint4*)(xl + q * 8) = z;
            }
        }
    }
    __syncthreads();

    const int g = lid >> 2, t = lid & 3;
    const int r0 = 16 * wid + g;
    float acc[8][4];
#pragma unroll
    for (int n0 = 0; n0 < 8; n0++)
#pragma unroll
        for (int j = 0; j < 4; j++) acc[n0][j] = 0.f;

    gemm_pass<0, 4, 72>(Xhi, Xlo, W1F, r0, t, lid, acc);

    const int nA = n0base + r0, nB = nA + 8;
    const bool vA = nA < N_NODES, vB = nB < N_NODES;
    const int gA = vA ? n2g[nA] : 0, gB = vB ? n2g[nB] : 0;

    uint32_t Ahi[4][4], Alo[4][4];
#pragma unroll
    for (int n0 = 0; n0 < 8; n0++) {
        const int col = n0 * 8 + 2 * t;
        float2 bbA = *(const float2*)(Bs + gA * 64 + col);
        float2 bbB = *(const float2*)(Bs + gB * 64 + col);
        const int ks2 = n0 >> 1, ib = (n0 & 1) * 2;
        split_frag(fmaxf(acc[n0][0] + bbA.x, 0.f), fmaxf(acc[n0][1] + bbA.y, 0.f),
                   fmaxf(acc[n0][2] + bbB.x, 0.f), fmaxf(acc[n0][3] + bbB.y, 0.f),
                   Ahi[ks2][ib], Ahi[ks2][ib + 1], Alo[ks2][ib], Alo[ks2][ib + 1]);
    }

    float d2[4][4];
#pragma unroll
    for (int nb = 0; nb < 4; nb++)
#pragma unroll
        for (int j = 0; j < 4; j++) d2[nb][j] = 0.f;

#pragma unroll
    for (int ks2 = 0; ks2 < 4; ks2++) {
        const uint4* wf = gWn2frag + (ks2 * 2) * 32 + lid;
#pragma unroll
        for (int p = 0; p < 2; p++) {
            uint4 w = wf[p * 32];
            mma_h(d2[2 * p], Ahi[ks2], w.x, w.y);
            mma_h(d2[2 * p], Alo[ks2], w.x, w.y);
            mma_h(d2[2 * p + 1], Ahi[ks2], w.z, w.w);
            mma_h(d2[2 * p + 1], Alo[ks2], w.z, w.w);
        }
    }

    // epilogue
    {
        const bool warpFull = (n0base + 16 * wid + 15) < N_NODES;
        int gFirst = 0, gLast = -1;
        if (warpFull) {
            gFirst = n2g[n0base + 16 * wid];
            gLast  = n2g[n0base + 16 * wid + 15];
        }
        float a0[4], a1[4], c0v[4], c1[4];
#pragma unroll
        for (int nb = 0; nb < 4; nb++) {
            const int col = nb * 8 + 2 * t;
            float2 bb = *(const float2*)(b2s + col);
            a0[nb] = d2[nb][0] + bb.x;  a1[nb] = d2[nb][1] + bb.y;
            c0v[nb] = d2[nb][2] + bb.x; c1[nb] = d2[nb][3] + bb.y;
            if (vA) *(float2*)(n_out + (size_t)nA * 32 + col) = make_float2(a0[nb], a1[nb]);
            if (vB) *(float2*)(n_out + (size_t)nB * 32 + col) = make_float2(c0v[nb], c1[nb]);
        }
        if (warpFull && gFirst == gLast) {
#pragma unroll
            for (int nb = 0; nb < 4; nb++) {
                float s0 = a0[nb] + c0v[nb];
                float s1 = a1[nb] + c1[nb];
#pragma unroll
                for (int m = 4; m <= 16; m <<= 1) {
                    s0 += __shfl_xor_sync(0xFFFFFFFFu, s0, m);
                    s1 += __shfl_xor_sync(0xFFFFFFFFu, s1, m);
                }
                if (g == 0) {
                    const int col = nb * 8 + 2 * t;
                    atomicAdd(&Ns[gFirst * 32 + col], s0);
                    atomicAdd(&Ns[gFirst * 32 + col + 1], s1);
                }
            }
        } else {
#pragma unroll
            for (int nb = 0; nb < 4; nb++) {
                const int col = nb * 8 + 2 * t;
                if (vA) {
                    atomicAdd(&Ns[gA * 32 + col], a0[nb]);
                    atomicAdd(&Ns[gA * 32 + col + 1], a1[nb]);
                }
                if (vB) {
                    atomicAdd(&Ns[gB * 32 + col], c0v[nb]);
                    atomicAdd(&Ns[gB * 32 + col + 1], c1[nb]);
                }
            }
        }
    }
    __syncthreads();
    atomicAdd(&g_ncomb[tid], Ns[tid]);

    // -------- last-block global MLP tail --------
    __shared__ unsigned s_done;
    __threadfence();
    __syncthreads();
    if (tid == 0) {
        unsigned tk = atomicAdd(&g_ticket, 1);
        s_done = (tk == gridDim.x - 1) ? 1u : 0u;
    }
    __syncthreads();
    if (!s_done) return;
    __threadfence();

    float* U   = (float*)(smem + 0);        // 768 f
    float* W1u = (float*)(smem + 4096);     // 6144 f
    float* W2u = (float*)(smem + 28672);    // 2048 f
    float* Hg  = (float*)(smem + 40960);    // 512 f

    for (int i = tid; i < B_GRAPH * 96; i += 256) {
        const int b = i / 96, c = i % 96;
        float v;
        if (c < 32)      v = g_ncomb[b * 32 + c];
        else if (c < 64) v = g_ecomb[b * 32 + (c - 32)];
        else             v = g_repr[b * 32 + (c - 64)];
        U[i] = v;
    }
    {
        const float4* wg = (const float4*)Wu1; float4* ws = (float4*)W1u;
        for (int i = tid; i < 1536; i += 256) ws[i] = wg[i];
        const float4* w2g = (const float4*)Wu2; float4* w2s = (float4*)W2u;
        for (int i = tid; i < 512; i += 256) w2s[i] = w2g[i];
    }
    __syncthreads();

    for (int idx = tid; idx < B_GRAPH * HID; idx += 256) {
        const int b = idx >> 6, j = idx & 63;
        float s = bu1[j];
#pragma unroll 8
        for (int k = 0; k < 96; k++) s += U[b * 96 + k] * W1u[k * 64 + j];
        Hg[idx] = fmaxf(s, 0.f);
    }
    __syncthreads();
    for (int idx = tid; idx < B_GRAPH * DOUT; idx += 256) {
        const int b = idx >> 5, c = idx & 31;
        float s = bu2[c];
#pragma unroll 8
        for (int k = 0; k < 64; k++) s += Hg[b * 64 + k] * W2u[k * 32 + c];
        g_out[idx] = s;
    }
}

extern "C" void kernel_launch(void* const* d_in, const int* in_sizes, int n_in,
                              void* d_out, int out_size)
{
    const float* edge_feat = (const float*)d_in[0];
    const float* node_feat = (const float*)d_in[1];
    const float* g_repr    = (const float*)d_in[2];
    const int*   src       = (const int*)d_in[3];
    const int*   dst       = (const int*)d_in[4];
    const int*   n2g       = (const int*)d_in[5];
    const int*   e2g       = (const int*)d_in[6];
    const float* W_e1 = (const float*)d_in[7];
    const float* b_e1 = (const float*)d_in[8];
    const float* W_e2 = (const float*)d_in[9];
    const float* b_e2 = (const float*)d_in[10];
    const float* W_n1 = (const float*)d_in[11];
    const float* b_n1 = (const float*)d_in[12];
    const float* W_n2 = (const float*)d_in[13];
    const float* b_n2 = (const float*)d_in[14];
    const float* W_u1 = (const float*)d_in[15];
    const float* b_u1 = (const float*)d_in[16];
    const float* W_u2 = (const float*)d_in[17];
    const float* b_u2 = (const float*)d_in[18];

    float* out = (float*)d_out;
    float* e_out = out;                                      // [E, 32]
    float* n_out = out + (size_t)N_EDGES * DOUT;             // [N, 32]
    float* g_out = out + (size_t)(N_EDGES + N_NODES) * DOUT; // [B, 32]

    cudaFuncSetAttribute(edge_kernel, cudaFuncAttributeMaxDynamicSharedMemorySize, SM_TOTAL);
    cudaFuncSetAttribute(node_kernel, cudaFuncAttributeMaxDynamicSharedMemorySize, NSM_TOTAL);

    zero_kernel<<<ZERO_BLOCKS + 8, 256>>>(W_e1, W_e2, W_n1, W_n2,
                                          b_e1, b_n1, g_repr);
    edge_kernel<<<N_EDGES / 128, 256, SM_TOTAL>>>(
        edge_feat, node_feat, src, dst, e2g, b_e2, e_out);
    node_kernel<<<(N_NODES + 127) / 128, 256, NSM_TOTAL>>>(
        node_feat, g_repr, n2g, b_n2,
        W_u1, b_u1, W_u2, b_u2, n_out, g_out);
}

// round 13
// speedup vs baseline: 1.0907x; 1.0440x over previous
#include <cuda_runtime.h>
#include <cuda_fp16.h>
#include <cstdint>

#define N_NODES 50000
#define N_EDGES 800000
#define B_GRAPH 8
#define HID 64
#define DOUT 32

__device__ __forceinline__ void mma_h(float* d, const uint32_t* a,
                                      uint32_t b0, uint32_t b1) {
    asm volatile(
        "mma.sync.aligned.m16n8k16.row.col.f32.f16.f16.f32 "
        "{%0,%1,%2,%3}, {%4,%5,%6,%7}, {%8,%9}, {%0,%1,%2,%3};"
        : "+f"(d[0]), "+f"(d[1]), "+f"(d[2]), "+f"(d[3])
        : "r"(a[0]), "r"(a[1]), "r"(a[2]), "r"(a[3]), "r"(b0), "r"(b1));
}
__device__ __forceinline__ void red2(float* p, float x, float y) {
    asm volatile("red.global.add.v2.f32 [%0], {%1, %2};"
                 :: "l"(p), "f"(x), "f"(y) : "memory");
}

// -------------------- scratch (device globals) --------------------
__device__ float g_h[(size_t)N_NODES * DOUT];
__device__ float g_ecomb[B_GRAPH * DOUT];
__device__ float g_ncomb[B_GRAPH * DOUT];
__device__ unsigned int g_ticket;
// fp16 hi-only weight fragments; each uint4 = two n-blocks {b0,b1} pairs
__device__ __align__(16) uint4 gW1frag[6 * 4 * 32];   // edge W1 (k 0..95)
__device__ __align__(16) uint4 gW2frag[4 * 2 * 32];   // edge W2
__device__ __align__(16) uint4 gWn1frag[4 * 4 * 32];  // node W1 (k 0..63)
__device__ __align__(16) uint4 gWn2frag[4 * 2 * 32];  // node W2
// per-graph fused biases: b1 + g_repr[g] @ W1[tail]  (exact fp32 fold)
__device__ __align__(16) float gBias1e[B_GRAPH * HID];
__device__ __align__(16) float gBias1n[B_GRAPH * HID];

__device__ __forceinline__ uint32_t hpack(float a, float b) {
    __half2 h = __floats2half2_rn(a, b);
    return *(uint32_t*)&h;
}

// -------------------- zero + prep --------------------
#define ZERO_BLOCKS 391    // 391*256*4 float4 >= 400k float4 (g_h)
#define PSTRIDE 2048       // 8 prep blocks * 256 threads

__global__ void zero_kernel(const float* __restrict__ W1,
                            const float* __restrict__ W2,
                            const float* __restrict__ Wn1,
                            const float* __restrict__ Wn2,
                            const float* __restrict__ b1e,
                            const float* __restrict__ b1n,
                            const float* __restrict__ g_repr) {
    if (blockIdx.x >= ZERO_BLOCKS) {
        const int pidx = (blockIdx.x - ZERO_BLOCKS) * 256 + threadIdx.x;
        if (pidx == 0) g_ticket = 0;
        if (pidx < 64) ((float4*)g_ecomb)[pidx] = make_float4(0.f, 0.f, 0.f, 0.f);
        else if (pidx < 128) ((float4*)g_ncomb)[pidx - 64] = make_float4(0.f, 0.f, 0.f, 0.f);
        // edge W1 fragments (hi-only fp16), k 0..95
        for (int idx = pidx; idx < 768; idx += PSTRIDE) {
            const int l = idx & 31, p = (idx >> 5) & 3, ks = idx >> 7;
            const int ne = p * 16 + (l >> 2), no = ne + 8;
            const int k0 = ks * 16 + 2 * (l & 3);
            uint4 f;
            f.x = hpack(W1[k0 * 64 + ne], W1[(k0 + 1) * 64 + ne]);
            f.y = hpack(W1[(k0 + 8) * 64 + ne], W1[(k0 + 9) * 64 + ne]);
            f.z = hpack(W1[k0 * 64 + no], W1[(k0 + 1) * 64 + no]);
            f.w = hpack(W1[(k0 + 8) * 64 + no], W1[(k0 + 9) * 64 + no]);
            gW1frag[idx] = f;
        }
        for (int idx = pidx; idx < 256; idx += PSTRIDE) {
            const int l = idx & 31, p = (idx >> 5) & 1, ks2 = idx >> 6;
            const int ne = p * 16 + (l >> 2), no = ne + 8;
            const int k0 = ks2 * 16 + 2 * (l & 3);
            uint4 f;
            f.x = hpack(W2[k0 * 32 + ne], W2[(k0 + 1) * 32 + ne]);
            f.y = hpack(W2[(k0 + 8) * 32 + ne], W2[(k0 + 9) * 32 + ne]);
            f.z = hpack(W2[k0 * 32 + no], W2[(k0 + 1) * 32 + no]);
            f.w = hpack(W2[(k0 + 8) * 32 + no], W2[(k0 + 9) * 32 + no]);
            gW2frag[idx] = f;
        }
        for (int idx = pidx; idx < 512; idx += PSTRIDE) {
            const int l = idx & 31, p = (idx >> 5) & 3, ks = idx >> 7;
            const int ne = p * 16 + (l >> 2), no = ne + 8;
            const int k0 = ks * 16 + 2 * (l & 3);
            uint4 f;
            f.x = hpack(Wn1[k0 * 64 + ne], Wn1[(k0 + 1) * 64 + ne]);
            f.y = hpack(Wn1[(k0 + 8) * 64 + ne], Wn1[(k0 + 9) * 64 + ne]);
            f.z = hpack(Wn1[k0 * 64 + no], Wn1[(k0 + 1) * 64 + no]);
            f.w = hpack(Wn1[(k0 + 8) * 64 + no], Wn1[(k0 + 9) * 64 + no]);
            gWn1frag[idx] = f;
        }
        for (int idx = pidx; idx < 256; idx += PSTRIDE) {
            const int l = idx & 31, p = (idx >> 5) & 1, ks2 = idx >> 6;
            const int ne = p * 16 + (l >> 2), no = ne + 8;
            const int k0 = ks2 * 16 + 2 * (l & 3);
            uint4 f;
            f.x = hpack(Wn2[k0 * 32 + ne], Wn2[(k0 + 1) * 32 + ne]);
            f.y = hpack(Wn2[(k0 + 8) * 32 + ne], Wn2[(k0 + 9) * 32 + ne]);
            f.z = hpack(Wn2[k0 * 32 + no], Wn2[(k0 + 1) * 32 + no]);
            f.w = hpack(Wn2[(k0 + 8) * 32 + no], Wn2[(k0 + 9) * 32 + no]);
            gWn2frag[idx] = f;
        }
        // fused per-graph biases (exact fp32)
        for (int idx = pidx; idx < B_GRAPH * HID; idx += PSTRIDE) {
            const int g = idx >> 6, n = idx & 63;
            float se = b1e[n], sn = b1n[n];
            for (int k = 0; k < 32; k++) {
                se += g_repr[g * 32 + k] * W1[(96 + k) * 64 + n];
                sn += g_repr[g * 32 + k] * Wn1[(64 + k) * 64 + n];
            }
            gBias1e[idx] = se;
            gBias1n[idx] = sn;
        }
        return;
    }
    // g_h zero: 4 float4 per thread (MLP=4)
    size_t base = (size_t)blockIdx.x * 1024 + threadIdx.x;
#pragma unroll
    for (int q = 0; q < 4; q++) {
        size_t i = base + q * 256;
        if (i < (size_t)N_NODES * DOUT / 4)
            ((float4*)g_h)[i] = make_float4(0.f, 0.f, 0.f, 0.f);
    }
}

// float8 -> fp16 hi/lo (X captured to ~2^-22)
__device__ __forceinline__ void cvt8h(float4 a, float4 b, uint4& hi, uint4& lo) {
    __half2 h0 = __floats2half2_rn(a.x, a.y);
    __half2 h1 = __floats2half2_rn(a.z, a.w);
    __half2 h2 = __floats2half2_rn(b.x, b.y);
    __half2 h3 = __floats2half2_rn(b.z, b.w);
    float2 f0 = __half22float2(h0), f1 = __half22float2(h1);
    float2 f2 = __half22float2(h2), f3 = __half22float2(h3);
    __half2 l0 = __floats2half2_rn(a.x - f0.x, a.y - f0.y);
    __half2 l1 = __floats2half2_rn(a.z - f1.x, a.w - f1.y);
    __half2 l2 = __floats2half2_rn(b.x - f2.x, b.y - f2.y);
    __half2 l3 = __floats2half2_rn(b.z - f3.x, b.w - f3.y);
    hi.x = *(uint32_t*)&h0; hi.y = *(uint32_t*)&h1; hi.z = *(uint32_t*)&h2; hi.w = *(uint32_t*)&h3;
    lo.x = *(uint32_t*)&l0; lo.y = *(uint32_t*)&l1; lo.z = *(uint32_t*)&l2; lo.w = *(uint32_t*)&l3;
}

__device__ __forceinline__ void split_frag(float v0, float v1, float v2, float v3,
                                           uint32_t& hA, uint32_t& hB,
                                           uint32_t& lA, uint32_t& lB) {
    __half2 a = __floats2half2_rn(v0, v1);
    __half2 b = __floats2half2_rn(v2, v3);
    float2 fa = __half22float2(a), fb = __half22float2(b);
    __half2 la = __floats2half2_rn(v0 - fa.x, v1 - fa.y);
    __half2 lb = __floats2half2_rn(v2 - fb.x, v3 - fb.y);
    hA = *(uint32_t*)&a; hB = *(uint32_t*)&b;
    lA = *(uint32_t*)&la; lB = *(uint32_t*)&lb;
}

// X tile GEMM pass over stride-72 fp16 hi/lo buffers; 2-term (Xhi+Xlo)*Whi.
template<int KS0, int NKS>
__device__ __forceinline__ void gemm_pass(
    const __half* __restrict__ Xhi, const __half* __restrict__ Xlo,
    const uint4* __restrict__ WF, int r0, int t, int lid, float acc[8][4])
{
#pragma unroll
    for (int ksl = 0; ksl < NKS; ksl++) {
        const int c0 = ksl * 16 + 2 * t;
        const __half* xh = Xhi + r0 * 72 + c0;
        const __half* xl = Xlo + r0 * 72 + c0;
        uint32_t ah[4], al[4];
        ah[0] = *(const uint32_t*)(xh);
        ah[1] = *(const uint32_t*)(xh + 8 * 72);
        ah[2] = *(const uint32_t*)(xh + 8);
        ah[3] = *(const uint32_t*)(xh + 8 * 72 + 8);
        al[0] = *(const uint32_t*)(xl);
        al[1] = *(const uint32_t*)(xl + 8 * 72);
        al[2] = *(const uint32_t*)(xl + 8);
        al[3] = *(const uint32_t*)(xl + 8 * 72 + 8);
        const uint4* wf = WF + ((KS0 + ksl) * 4) * 32 + lid;
#pragma unroll
        for (int p = 0; p < 4; p++) {
            uint4 w = wf[p * 32];
            mma_h(acc[2 * p], ah, w.x, w.y);
            mma_h(acc[2 * p], al, w.x, w.y);
            mma_h(acc[2 * p + 1], ah, w.z, w.w);
            mma_h(acc[2 * p + 1], al, w.z, w.w);
        }
    }
}

// ================== EDGE KERNEL (R9 structure + smem W2) ==================
#define SM_XHI   0        // 128 x 72 fp16 = 18432
#define SM_XLO   18432
#define SM_W1F   36864    // 768 uint4 = 12288
#define SM_BIAS  49152    // 512 f = 2048
#define SM_B2    51200    // 128
#define SM_ES    51328    // 1024
#define SM_W2F   52352    // 256 uint4 = 4096
#define SM_TOTAL 56448

__global__ void __launch_bounds__(256, 3) edge_kernel(
    const float* __restrict__ edge_feat, const float* __restrict__ node_feat,
    const int* __restrict__ src, const int* __restrict__ dst,
    const int* __restrict__ e2g, const float* __restrict__ b2,
    float* __restrict__ e_out)
{
    extern __shared__ unsigned char smem[];
    const int tid = threadIdx.x;
    const int wid = tid >> 5, lid = tid & 31;

    __half* Xhi = (__half*)(smem + SM_XHI);
    __half* Xlo = (__half*)(smem + SM_XLO);
    const uint4* W1F = (const uint4*)(smem + SM_W1F);
    const uint4* W2F = (const uint4*)(smem + SM_W2F);
    float* Bs  = (float*)(smem + SM_BIAS);
    float* b2s = (float*)(smem + SM_B2);
    float* Es  = (float*)(smem + SM_ES);

    {
        uint4* d1 = (uint4*)(smem + SM_W1F);
        for (int i = tid; i < 768; i += 256) d1[i] = gW1frag[i];
        uint4* d2 = (uint4*)(smem + SM_W2F);
        if (tid < 256) d2[tid] = gW2frag[tid];
        for (int i = tid; i < 512; i += 256) Bs[i] = gBias1e[i];
        if (tid < DOUT) b2s[tid] = b2[tid];
        Es[tid] = 0.f;
    }

    const size_t e0 = (size_t)blockIdx.x * 128;
    const int r = tid >> 1, half = tid & 1;
    const size_t eg = e0 + r;
    const int si = src[eg], di = dst[eg];

    // prefetch pass-2 gather (node_feat[dst], 16 cols per thread)
    float4 pf[4];
    {
        const float4* pd = (const float4*)(node_feat + (size_t)di * 32) + 4 * half;
        pf[0] = pd[0]; pf[1] = pd[1]; pf[2] = pd[2]; pf[3] = pd[3];
    }

    // gather pass 1: k 0..63 = edge_feat || node_feat[src]
    {
        const float4* p = (const float4*)(half ? node_feat + (size_t)si * 32
                                               : edge_feat + eg * 32);
        __half* xh = Xhi + r * 72 + half * 32;
        __half* xl = Xlo + r * 72 + half * 32;
#pragma unroll
        for (int q = 0; q < 4; q++) {
            uint4 hi, lo;
            cvt8h(p[2 * q], p[2 * q + 1], hi, lo);
            *(uint4*)(xh + q * 8) = hi;
            *(uint4*)(xl + q * 8) = lo;
        }
    }
    __syncthreads();

    const int g = lid >> 2, t = lid & 3;
    const int r0 = 16 * wid + g;
    float acc[8][4];
#pragma unroll
    for (int n0 = 0; n0 < 8; n0++)
#pragma unroll
        for (int j = 0; j < 4; j++) acc[n0][j] = 0.f;

    gemm_pass<0, 4>(Xhi, Xlo, W1F, r0, t, lid, acc);
    __syncthreads();

    // store pass-2 gather (cols 0..31 now hold k 64..95 = node_feat[dst])
    {
        __half* xh = Xhi + r * 72 + half * 16;
        __half* xl = Xlo + r * 72 + half * 16;
        uint4 hi, lo;
        cvt8h(pf[0], pf[1], hi, lo);
        *(uint4*)(xh) = hi; *(uint4*)(xl) = lo;
        cvt8h(pf[2], pf[3], hi, lo);
        *(uint4*)(xh + 8) = hi; *(uint4*)(xl + 8) = lo;
    }
    __syncthreads();

    const size_t eA = e0 + r0, eB = eA + 8;
    const int gA = e2g[eA], gB = e2g[eB];

    gemm_pass<4, 2>(Xhi, Xlo, W1F, r0, t, lid, acc);

    // fused bias + relu + register split (fp16 hi/lo A fragments)
    uint32_t Ahi[4][4], Alo[4][4];
#pragma unroll
    for (int n0 = 0; n0 < 8; n0++) {
        const int col = n0 * 8 + 2 * t;
        float2 bbA = *(const float2*)(Bs + gA * 64 + col);
        float2 bbB = *(const float2*)(Bs + gB * 64 + col);
        const int ks2 = n0 >> 1, ib = (n0 & 1) * 2;
        split_frag(fmaxf(acc[n0][0] + bbA.x, 0.f), fmaxf(acc[n0][1] + bbA.y, 0.f),
                   fmaxf(acc[n0][2] + bbB.x, 0.f), fmaxf(acc[n0][3] + bbB.y, 0.f),
                   Ahi[ks2][ib], Ahi[ks2][ib + 1], Alo[ks2][ib], Alo[ks2][ib + 1]);
    }

    // GEMM2: K=64, 2-term, weight fragments from smem
    float d2[4][4];
#pragma unroll
    for (int nb = 0; nb < 4; nb++)
#pragma unroll
        for (int j = 0; j < 4; j++) d2[nb][j] = 0.f;

#pragma unroll
    for (int ks2 = 0; ks2 < 4; ks2++) {
        const uint4* wf = W2F + (ks2 * 2) * 32 + lid;
#pragma unroll
        for (int p = 0; p < 2; p++) {
            uint4 w = wf[p * 32];
            mma_h(d2[2 * p], Ahi[ks2], w.x, w.y);
            mma_h(d2[2 * p], Alo[ks2], w.x, w.y);
            mma_h(d2[2 * p + 1], Ahi[ks2], w.z, w.w);
            mma_h(d2[2 * p + 1], Alo[ks2], w.z, w.w);
        }
    }

    // epilogue
    {
        const int dA = dst[eA], dB = dst[eB];
        const int gFirst = e2g[e0 + 16 * wid];
        const int gLast  = e2g[e0 + 16 * wid + 15];
        float* hA = g_h + (size_t)dA * 32;
        float* hB = g_h + (size_t)dB * 32;
        float* oA = e_out + eA * 32;
        float* oB = e_out + eB * 32;
        float a0[4], a1[4], c0v[4], c1[4];
#pragma unroll
        for (int nb = 0; nb < 4; nb++) {
            const int col = nb * 8 + 2 * t;
            float2 bb = *(const float2*)(b2s + col);
            a0[nb] = d2[nb][0] + bb.x;  a1[nb] = d2[nb][1] + bb.y;
            c0v[nb] = d2[nb][2] + bb.x; c1[nb] = d2[nb][3] + bb.y;
            *(float2*)(oA + col) = make_float2(a0[nb], a1[nb]);
            *(float2*)(oB + col) = make_float2(c0v[nb], c1[nb]);
            red2(hA + col, a0[nb], a1[nb]);
            red2(hB + col, c0v[nb], c1[nb]);
        }
        if (gFirst == gLast) {
#pragma unroll
            for (int nb = 0; nb < 4; nb++) {
                float s0 = a0[nb] + c0v[nb];
                float s1 = a1[nb] + c1[nb];
#pragma unroll
                for (int m = 4; m <= 16; m <<= 1) {
                    s0 += __shfl_xor_sync(0xFFFFFFFFu, s0, m);
                    s1 += __shfl_xor_sync(0xFFFFFFFFu, s1, m);
                }
                if (g == 0) {
                    const int col = nb * 8 + 2 * t;
                    atomicAdd(&Es[gFirst * 32 + col], s0);
                    atomicAdd(&Es[gFirst * 32 + col + 1], s1);
                }
            }
        } else {
#pragma unroll
            for (int nb = 0; nb < 4; nb++) {
                const int col = nb * 8 + 2 * t;
                atomicAdd(&Es[gA * 32 + col], a0[nb]);
                atomicAdd(&Es[gA * 32 + col + 1], a1[nb]);
                atomicAdd(&Es[gB * 32 + col], c0v[nb]);
                atomicAdd(&Es[gB * 32 + col + 1], c1[nb]);
            }
        }
    }
    __syncthreads();
    atomicAdd(&g_ecomb[tid], Es[tid]);
}

// ================== NODE KERNEL + global tail ==================
#define NSM_XHI   0        // 128 x 72 fp16 = 18432
#define NSM_XLO   18432
#define NSM_W1F   36864    // 512 uint4 = 8192
#define NSM_BIAS  45056    // 2048
#define NSM_B2    47104    // 128
#define NSM_NS    47232    // 1024
#define NSM_W2F   48256    // 256 uint4 = 4096
#define NSM_TOTAL 52352

__global__ void __launch_bounds__(256, 3) node_kernel(
    const float* __restrict__ node_feat, const float* __restrict__ g_repr,
    const int* __restrict__ n2g, const float* __restrict__ b2,
    const float* __restrict__ Wu1, const float* __restrict__ bu1,
    const float* __restrict__ Wu2, const float* __restrict__ bu2,
    float* __restrict__ n_out, float* __restrict__ g_out)
{
    extern __shared__ unsigned char smem[];
    const int tid = threadIdx.x;
    const int wid = tid >> 5, lid = tid & 31;

    __half* Xhi = (__half*)(smem + NSM_XHI);
    __half* Xlo = (__half*)(smem + NSM_XLO);
    const uint4* W1F = (const uint4*)(smem + NSM_W1F);
    const uint4* W2F = (const uint4*)(smem + NSM_W2F);
    float* Bs  = (float*)(smem + NSM_BIAS);
    float* b2s = (float*)(smem + NSM_B2);
    float* Ns  = (float*)(smem + NSM_NS);

    {
        uint4* d1 = (uint4*)(smem + NSM_W1F);
        for (int i = tid; i < 512; i += 256) d1[i] = gWn1frag[i];
        uint4* d2 = (uint4*)(smem + NSM_W2F);
        if (tid < 256) d2[tid] = gWn2frag[tid];
        for (int i = tid; i < 512; i += 256) Bs[i] = gBias1n[i];
        if (tid < DOUT) b2s[tid] = b2[tid];
        Ns[tid] = 0.f;
    }

    const int n0base = blockIdx.x * 128;

    // gather: k 0..63 = node_feat || g_h
    {
        const int r = tid >> 1, half = tid & 1;
        const int node = n0base + r;
        __half* xh = Xhi + r * 72 + half * 32;
        __half* xl = Xlo + r * 72 + half * 32;
        if (node < N_NODES) {
            const float4* p = (const float4*)((half ? g_h : node_feat) + (size_t)node * 32);
#pragma unroll
            for (int q = 0; q < 4; q++) {
                uint4 hi, lo;
                cvt8h(p[2 * q], p[2 * q + 1], hi, lo);
                *(uint4*)(xh + q * 8) = hi;
                *(uint4*)(xl + q * 8) = lo;
            }
        } else {
            const uint4 z = make_uint4(0, 0, 0, 0);
#pragma unroll
            for (int q = 0; q < 4; q++) {
                *(uint4*)(xh + q * 8) = z;
                *(uint4*)(xl + q * 8) = z;
            }
        }
    }
    __syncthreads();

    const int g = lid >> 2, t = lid & 3;
    const int r0 = 16 * wid + g;
    float acc[8][4];
#pragma unroll
    for (int n0 = 0; n0 < 8; n0++)
#pragma unroll
        for (int j = 0; j < 4; j++) acc[n0][j] = 0.f;

    gemm_pass<0, 4>(Xhi, Xlo, W1F, r0, t, lid, acc);

    const int nA = n0base + r0, nB = nA + 8;
    const bool vA = nA < N_NODES, vB = nB < N_NODES;
    const int gA = vA ? n2g[nA] : 0, gB = vB ? n2g[nB] : 0;

    uint32_t Ahi[4][4], Alo[4][4];
#pragma unroll
    for (int n0 = 0; n0 < 8; n0++) {
        const int col = n0 * 8 + 2 * t;
        float2 bbA = *(const float2*)(Bs + gA * 64 + col);
        float2 bbB = *(const float2*)(Bs + gB * 64 + col);
        const int ks2 = n0 >> 1, ib = (n0 & 1) * 2;
        split_frag(fmaxf(acc[n0][0] + bbA.x, 0.f), fmaxf(acc[n0][1] + bbA.y, 0.f),
                   fmaxf(acc[n0][2] + bbB.x, 0.f), fmaxf(acc[n0][3] + bbB.y, 0.f),
                   Ahi[ks2][ib], Ahi[ks2][ib + 1], Alo[ks2][ib], Alo[ks2][ib + 1]);
    }

    float d2[4][4];
#pragma unroll
    for (int nb = 0; nb < 4; nb++)
#pragma unroll
        for (int j = 0; j < 4; j++) d2[nb][j] = 0.f;

#pragma unroll
    for (int ks2 = 0; ks2 < 4; ks2++) {
        const uint4* wf = W2F + (ks2 * 2) * 32 + lid;
#pragma unroll
        for (int p = 0; p < 2; p++) {
            uint4 w = wf[p * 32];
            mma_h(d2[2 * p], Ahi[ks2], w.x, w.y);
            mma_h(d2[2 * p], Alo[ks2], w.x, w.y);
            mma_h(d2[2 * p + 1], Ahi[ks2], w.z, w.w);
            mma_h(d2[2 * p + 1], Alo[ks2], w.z, w.w);
        }
    }

    // epilogue
    {
        const bool warpFull = (n0base + 16 * wid + 15) < N_NODES;
        int gFirst = 0, gLast = -1;
        if (warpFull) {
            gFirst = n2g[n0base + 16 * wid];
            gLast  = n2g[n0base + 16 * wid + 15];
        }
        float a0[4], a1[4], c0v[4], c1[4];
#pragma unroll
        for (int nb = 0; nb < 4; nb++) {
            const int col = nb * 8 + 2 * t;
            float2 bb = *(const float2*)(b2s + col);
            a0[nb] = d2[nb][0] + bb.x;  a1[nb] = d2[nb][1] + bb.y;
            c0v[nb] = d2[nb][2] + bb.x; c1[nb] = d2[nb][3] + bb.y;
            if (vA) *(float2*)(n_out + (size_t)nA * 32 + col) = make_float2(a0[nb], a1[nb]);
            if (vB) *(float2*)(n_out + (size_t)nB * 32 + col) = make_float2(c0v[nb], c1[nb]);
        }
        if (warpFull && gFirst == gLast) {
#pragma unroll
            for (int nb = 0; nb < 4; nb++) {
                float s0 = a0[nb] + c0v[nb];
                float s1 = a1[nb] + c1[nb];
#pragma unroll
                for (int m = 4; m <= 16; m <<= 1) {
                    s0 += __shfl_xor_sync(0xFFFFFFFFu, s0, m);
                    s1 += __shfl_xor_sync(0xFFFFFFFFu, s1, m);
                }
                if (g == 0) {
                    const int col = nb * 8 + 2 * t;
                    atomicAdd(&Ns[gFirst * 32 + col], s0);
                    atomicAdd(&Ns[gFirst * 32 + col + 1], s1);
                }
            }
        } else {
#pragma unroll
            for (int nb = 0; nb < 4; nb++) {
                const int col = nb * 8 + 2 * t;
                if (vA) {
                    atomicAdd(&Ns[gA * 32 + col], a0[nb]);
                    atomicAdd(&Ns[gA * 32 + col + 1], a1[nb]);
                }
                if (vB) {
                    atomicAdd(&Ns[gB * 32 + col], c0v[nb]);
                    atomicAdd(&Ns[gB * 32 + col + 1], c1[nb]);
                }
            }
        }
    }
    __syncthreads();
    atomicAdd(&g_ncomb[tid], Ns[tid]);

    // -------- last-block global MLP tail --------
    __shared__ unsigned s_done;
    __threadfence();
    __syncthreads();
    if (tid == 0) {
        unsigned tk = atomicAdd(&g_ticket, 1);
        s_done = (tk == gridDim.x - 1) ? 1u : 0u;
    }
    __syncthreads();
    if (!s_done) return;
    __threadfence();

    float* U   = (float*)(smem + 0);        // 768 f
    float* W1u = (float*)(smem + 4096);     // 6144 f
    float* W2u = (float*)(smem + 28672);    // 2048 f
    float* Hg  = (float*)(smem + 40960);    // 512 f

    for (int i = tid; i < B_GRAPH * 96; i += 256) {
        const int b = i / 96, c = i % 96;
        float v;
        if (c < 32)      v = g_ncomb[b * 32 + c];
        else if (c < 64) v = g_ecomb[b * 32 + (c - 32)];
        else             v = g_repr[b * 32 + (c - 64)];
        U[i] = v;
    }
    {
        const float4* wg = (const float4*)Wu1; float4* ws = (float4*)W1u;
        for (int i = tid; i < 1536; i += 256) ws[i] = wg[i];
        const float4* w2g = (const float4*)Wu2; float4* w2s = (float4*)W2u;
        for (int i = tid; i < 512; i += 256) w2s[i] = w2g[i];
    }
    __syncthreads();

    for (int idx = tid; idx < B_GRAPH * HID; idx += 256) {
        const int b = idx >> 6, j = idx & 63;
        float s = bu1[j];
#pragma unroll 8
        for (int k = 0; k < 96; k++) s += U[b * 96 + k] * W1u[k * 64 + j];
        Hg[idx] = fmaxf(s, 0.f);
    }
    __syncthreads();
    for (int idx = tid; idx < B_GRAPH * DOUT; idx += 256) {
        const int b = idx >> 5, c = idx & 31;
        float s = bu2[c];
#pragma unroll 8
        for (int k = 0; k < 64; k++) s += Hg[b * 64 + k] * W2u[k * 32 + c];
        g_out[idx] = s;
    }
}

extern "C" void kernel_launch(void* const* d_in, const int* in_sizes, int n_in,
                              void* d_out, int out_size)
{
    const float* edge_feat = (const float*)d_in[0];
    const float* node_feat = (const float*)d_in[1];
    const float* g_repr    = (const float*)d_in[2];
    const int*   src       = (const int*)d_in[3];
    const int*   dst       = (const int*)d_in[4];
    const int*   n2g       = (const int*)d_in[5];
    const int*   e2g       = (const int*)d_in[6];
    const float* W_e1 = (const float*)d_in[7];
    const float* b_e1 = (const float*)d_in[8];
    const float* W_e2 = (const float*)d_in[9];
    const float* b_e2 = (const float*)d_in[10];
    const float* W_n1 = (const float*)d_in[11];
    const float* b_n1 = (const float*)d_in[12];
    const float* W_n2 = (const float*)d_in[13];
    const float* b_n2 = (const float*)d_in[14];
    const float* W_u1 = (const float*)d_in[15];
    const float* b_u1 = (const float*)d_in[16];
    const float* W_u2 = (const float*)d_in[17];
    const float* b_u2 = (const float*)d_in[18];

    float* out = (float*)d_out;
    float* e_out = out;                                      // [E, 32]
    float* n_out = out + (size_t)N_EDGES * DOUT;             // [N, 32]
    float* g_out = out + (size_t)(N_EDGES + N_NODES) * DOUT; // [B, 32]

    cudaFuncSetAttribute(edge_kernel, cudaFuncAttributeMaxDynamicSharedMemorySize, SM_TOTAL);
    cudaFuncSetAttribute(node_kernel, cudaFuncAttributeMaxDynamicSharedMemorySize, NSM_TOTAL);

    zero_kernel<<<ZERO_BLOCKS + 8, 256>>>(W_e1, W_e2, W_n1, W_n2,
                                          b_e1, b_n1, g_repr);
    edge_kernel<<<N_EDGES / 128, 256, SM_TOTAL>>>(
        edge_feat, node_feat, src, dst, e2g, b_e2, e_out);
    node_kernel<<<(N_NODES + 127) / 128, 256, NSM_TOTAL>>>(
        node_feat, g_repr, n2g, b_n2,
        W_u1, b_u1, W_u2, b_u2, n_out, g_out);
}

// round 14
// speedup vs baseline: 1.1506x; 1.0549x over previous
#include <cuda_runtime.h>
#include <cuda_fp16.h>
#include <cstdint>

#define N_NODES 50000
#define N_EDGES 800000
#define B_GRAPH 8
#define HID 64
#define DOUT 32

__device__ __forceinline__ void mma_h(float* d, const uint32_t* a,
                                      uint32_t b0, uint32_t b1) {
    asm volatile(
        "mma.sync.aligned.m16n8k16.row.col.f32.f16.f16.f32 "
        "{%0,%1,%2,%3}, {%4,%5,%6,%7}, {%8,%9}, {%0,%1,%2,%3};"
        : "+f"(d[0]), "+f"(d[1]), "+f"(d[2]), "+f"(d[3])
        : "r"(a[0]), "r"(a[1]), "r"(a[2]), "r"(a[3]), "r"(b0), "r"(b1));
}
__device__ __forceinline__ void red2(float* p, float x, float y) {
    asm volatile("red.global.add.v2.f32 [%0], {%1, %2};"
                 :: "l"(p), "f"(x), "f"(y) : "memory");
}

// -------------------- scratch (device globals) --------------------
__device__ float g_h[(size_t)N_NODES * DOUT];
__device__ float g_ecomb[B_GRAPH * DOUT];
__device__ float g_ncomb[B_GRAPH * DOUT];
__device__ unsigned int g_ticket;
// fp16 hi-only weight fragments; each uint4 = two n-blocks {b0,b1} pairs
__device__ __align__(16) uint4 gW1frag[6 * 4 * 32];   // edge W1 (k 0..95)
__device__ __align__(16) uint4 gW2frag[4 * 2 * 32];   // edge W2
__device__ __align__(16) uint4 gWn1frag[4 * 4 * 32];  // node W1 (k 0..63)
__device__ __align__(16) uint4 gWn2frag[4 * 2 * 32];  // node W2
// per-graph fused biases: b1 + g_repr[g] @ W1[tail]  (exact fp32 fold)
__device__ __align__(16) float gBias1e[B_GRAPH * HID];
__device__ __align__(16) float gBias1n[B_GRAPH * HID];

__device__ __forceinline__ uint32_t hpack(float a, float b) {
    __half2 h = __floats2half2_rn(a, b);
    return *(uint32_t*)&h;
}

// -------------------- zero + prep --------------------
#define ZERO_BLOCKS 391    // 391*256*4 float4 >= 400k float4 (g_h)
#define PSTRIDE 2048       // 8 prep blocks * 256 threads

__global__ void zero_kernel(const float* __restrict__ W1,
                            const float* __restrict__ W2,
                            const float* __restrict__ Wn1,
                            const float* __restrict__ Wn2,
                            const float* __restrict__ b1e,
                            const float* __restrict__ b1n,
                            const float* __restrict__ g_repr) {
    if (blockIdx.x >= ZERO_BLOCKS) {
        const int pidx = (blockIdx.x - ZERO_BLOCKS) * 256 + threadIdx.x;
        if (pidx == 0) g_ticket = 0;
        if (pidx < 64) ((float4*)g_ecomb)[pidx] = make_float4(0.f, 0.f, 0.f, 0.f);
        else if (pidx < 128) ((float4*)g_ncomb)[pidx - 64] = make_float4(0.f, 0.f, 0.f, 0.f);
        // edge W1 fragments (hi-only fp16), k 0..95
        for (int idx = pidx; idx < 768; idx += PSTRIDE) {
            const int l = idx & 31, p = (idx >> 5) & 3, ks = idx >> 7;
            const int ne = p * 16 + (l >> 2), no = ne + 8;
            const int k0 = ks * 16 + 2 * (l & 3);
            uint4 f;
            f.x = hpack(W1[k0 * 64 + ne], W1[(k0 + 1) * 64 + ne]);
            f.y = hpack(W1[(k0 + 8) * 64 + ne], W1[(k0 + 9) * 64 + ne]);
            f.z = hpack(W1[k0 * 64 + no], W1[(k0 + 1) * 64 + no]);
            f.w = hpack(W1[(k0 + 8) * 64 + no], W1[(k0 + 9) * 64 + no]);
            gW1frag[idx] = f;
        }
        for (int idx = pidx; idx < 256; idx += PSTRIDE) {
            const int l = idx & 31, p = (idx >> 5) & 1, ks2 = idx >> 6;
            const int ne = p * 16 + (l >> 2), no = ne + 8;
            const int k0 = ks2 * 16 + 2 * (l & 3);
            uint4 f;
            f.x = hpack(W2[k0 * 32 + ne], W2[(k0 + 1) * 32 + ne]);
            f.y = hpack(W2[(k0 + 8) * 32 + ne], W2[(k0 + 9) * 32 + ne]);
            f.z = hpack(W2[k0 * 32 + no], W2[(k0 + 1) * 32 + no]);
            f.w = hpack(W2[(k0 + 8) * 32 + no], W2[(k0 + 9) * 32 + no]);
            gW2frag[idx] = f;
        }
        for (int idx = pidx; idx < 512; idx += PSTRIDE) {
            const int l = idx & 31, p = (idx >> 5) & 3, ks = idx >> 7;
            const int ne = p * 16 + (l >> 2), no = ne + 8;
            const int k0 = ks * 16 + 2 * (l & 3);
            uint4 f;
            f.x = hpack(Wn1[k0 * 64 + ne], Wn1[(k0 + 1) * 64 + ne]);
            f.y = hpack(Wn1[(k0 + 8) * 64 + ne], Wn1[(k0 + 9) * 64 + ne]);
            f.z = hpack(Wn1[k0 * 64 + no], Wn1[(k0 + 1) * 64 + no]);
            f.w = hpack(Wn1[(k0 + 8) * 64 + no], Wn1[(k0 + 9) * 64 + no]);
            gWn1frag[idx] = f;
        }
        for (int idx = pidx; idx < 256; idx += PSTRIDE) {
            const int l = idx & 31, p = (idx >> 5) & 1, ks2 = idx >> 6;
            const int ne = p * 16 + (l >> 2), no = ne + 8;
            const int k0 = ks2 * 16 + 2 * (l & 3);
            uint4 f;
            f.x = hpack(Wn2[k0 * 32 + ne], Wn2[(k0 + 1) * 32 + ne]);
            f.y = hpack(Wn2[(k0 + 8) * 32 + ne], Wn2[(k0 + 9) * 32 + ne]);
            f.z = hpack(Wn2[k0 * 32 + no], Wn2[(k0 + 1) * 32 + no]);
            f.w = hpack(Wn2[(k0 + 8) * 32 + no], Wn2[(k0 + 9) * 32 + no]);
            gWn2frag[idx] = f;
        }
        // fused per-graph biases (exact fp32)
        for (int idx = pidx; idx < B_GRAPH * HID; idx += PSTRIDE) {
            const int g = idx >> 6, n = idx & 63;
            float se = b1e[n], sn = b1n[n];
            for (int k = 0; k < 32; k++) {
                se += g_repr[g * 32 + k] * W1[(96 + k) * 64 + n];
                sn += g_repr[g * 32 + k] * Wn1[(64 + k) * 64 + n];
            }
            gBias1e[idx] = se;
            gBias1n[idx] = sn;
        }
        return;
    }
    // g_h zero: 4 float4 per thread (MLP=4)
    size_t base = (size_t)blockIdx.x * 1024 + threadIdx.x;
#pragma unroll
    for (int q = 0; q < 4; q++) {
        size_t i = base + q * 256;
        if (i < (size_t)N_NODES * DOUT / 4)
            ((float4*)g_h)[i] = make_float4(0.f, 0.f, 0.f, 0.f);
    }
}

// float8 -> fp16 hi only
__device__ __forceinline__ uint4 cvt8h1(float4 a, float4 b) {
    __half2 h0 = __floats2half2_rn(a.x, a.y);
    __half2 h1 = __floats2half2_rn(a.z, a.w);
    __half2 h2 = __floats2half2_rn(b.x, b.y);
    __half2 h3 = __floats2half2_rn(b.z, b.w);
    uint4 hi;
    hi.x = *(uint32_t*)&h0; hi.y = *(uint32_t*)&h1;
    hi.z = *(uint32_t*)&h2; hi.w = *(uint32_t*)&h3;
    return hi;
}

// X tile GEMM pass over stride-72 fp16 hi buffer; single-term X*Whi.
template<int KS0, int NKS>
__device__ __forceinline__ void gemm_pass(
    const __half* __restrict__ Xhi,
    const uint4* __restrict__ WF, int r0, int t, int lid, float acc[8][4])
{
#pragma unroll
    for (int ksl = 0; ksl < NKS; ksl++) {
        const int c0 = ksl * 16 + 2 * t;
        const __half* xh = Xhi + r0 * 72 + c0;
        uint32_t ah[4];
        ah[0] = *(const uint32_t*)(xh);
        ah[1] = *(const uint32_t*)(xh + 8 * 72);
        ah[2] = *(const uint32_t*)(xh + 8);
        ah[3] = *(const uint32_t*)(xh + 8 * 72 + 8);
        const uint4* wf = WF + ((KS0 + ksl) * 4) * 32 + lid;
#pragma unroll
        for (int p = 0; p < 4; p++) {
            uint4 w = wf[p * 32];
            mma_h(acc[2 * p], ah, w.x, w.y);
            mma_h(acc[2 * p + 1], ah, w.z, w.w);
        }
    }
}

// ================== EDGE KERNEL (single-term fp16) ==================
#define SM_XHI   0        // 128 x 72 fp16 = 18432
#define SM_W1F   18432    // 768 uint4 = 12288
#define SM_W2F   30720    // 256 uint4 = 4096
#define SM_BIAS  34816    // 512 f = 2048
#define SM_B2    36864    // 128
#define SM_ES    36992    // 1024
#define SM_TOTAL 38016

__global__ void __launch_bounds__(256, 3) edge_kernel(
    const float* __restrict__ edge_feat, const float* __restrict__ node_feat,
    const int* __restrict__ src, const int* __restrict__ dst,
    const int* __restrict__ e2g, const float* __restrict__ b2,
    float* __restrict__ e_out)
{
    extern __shared__ unsigned char smem[];
    const int tid = threadIdx.x;
    const int wid = tid >> 5, lid = tid & 31;

    __half* Xhi = (__half*)(smem + SM_XHI);
    const uint4* W1F = (const uint4*)(smem + SM_W1F);
    const uint4* W2F = (const uint4*)(smem + SM_W2F);
    float* Bs  = (float*)(smem + SM_BIAS);
    float* b2s = (float*)(smem + SM_B2);
    float* Es  = (float*)(smem + SM_ES);

    {
        uint4* d1 = (uint4*)(smem + SM_W1F);
        for (int i = tid; i < 768; i += 256) d1[i] = gW1frag[i];
        uint4* d2 = (uint4*)(smem + SM_W2F);
        if (tid < 256) d2[tid] = gW2frag[tid];
        for (int i = tid; i < 512; i += 256) Bs[i] = gBias1e[i];
        if (tid < DOUT) b2s[tid] = b2[tid];
        Es[tid] = 0.f;
    }

    const size_t e0 = (size_t)blockIdx.x * 128;
    const int r = tid >> 1, half = tid & 1;
    const size_t eg = e0 + r;
    const int si = src[eg], di = dst[eg];

    // prefetch pass-2 gather (node_feat[dst], 16 cols per thread)
    float4 pf[4];
    {
        const float4* pd = (const float4*)(node_feat + (size_t)di * 32) + 4 * half;
        pf[0] = pd[0]; pf[1] = pd[1]; pf[2] = pd[2]; pf[3] = pd[3];
    }

    // gather pass 1: k 0..63 = edge_feat || node_feat[src]
    {
        const float4* p = (const float4*)(half ? node_feat + (size_t)si * 32
                                               : edge_feat + eg * 32);
        __half* xh = Xhi + r * 72 + half * 32;
#pragma unroll
        for (int q = 0; q < 4; q++)
            *(uint4*)(xh + q * 8) = cvt8h1(p[2 * q], p[2 * q + 1]);
    }
    __syncthreads();

    const int g = lid >> 2, t = lid & 3;
    const int r0 = 16 * wid + g;
    float acc[8][4];
#pragma unroll
    for (int n0 = 0; n0 < 8; n0++)
#pragma unroll
        for (int j = 0; j < 4; j++) acc[n0][j] = 0.f;

    gemm_pass<0, 4>(Xhi, W1F, r0, t, lid, acc);
    __syncthreads();

    // store pass-2 gather (cols 0..31 now hold k 64..95 = node_feat[dst])
    {
        __half* xh = Xhi + r * 72 + half * 16;
        *(uint4*)(xh)     = cvt8h1(pf[0], pf[1]);
        *(uint4*)(xh + 8) = cvt8h1(pf[2], pf[3]);
    }
    __syncthreads();

    const size_t eA = e0 + r0, eB = eA + 8;
    const int gA = e2g[eA], gB = e2g[eB];

    gemm_pass<4, 2>(Xhi, W1F, r0, t, lid, acc);

    // fused bias + relu -> fp16 A fragments (single-term)
    uint32_t Ahi[4][4];
#pragma unroll
    for (int n0 = 0; n0 < 8; n0++) {
        const int col = n0 * 8 + 2 * t;
        float2 bbA = *(const float2*)(Bs + gA * 64 + col);
        float2 bbB = *(const float2*)(Bs + gB * 64 + col);
        const int ks2 = n0 >> 1, ib = (n0 & 1) * 2;
        Ahi[ks2][ib]     = hpack(fmaxf(acc[n0][0] + bbA.x, 0.f),
                                 fmaxf(acc[n0][1] + bbA.y, 0.f));
        Ahi[ks2][ib + 1] = hpack(fmaxf(acc[n0][2] + bbB.x, 0.f),
                                 fmaxf(acc[n0][3] + bbB.y, 0.f));
    }

    // GEMM2: K=64, single-term, weight fragments from smem
    float d2[4][4];
#pragma unroll
    for (int nb = 0; nb < 4; nb++)
#pragma unroll
        for (int j = 0; j < 4; j++) d2[nb][j] = 0.f;

#pragma unroll
    for (int ks2 = 0; ks2 < 4; ks2++) {
        const uint4* wf = W2F + (ks2 * 2) * 32 + lid;
#pragma unroll
        for (int p = 0; p < 2; p++) {
            uint4 w = wf[p * 32];
            mma_h(d2[2 * p], Ahi[ks2], w.x, w.y);
            mma_h(d2[2 * p + 1], Ahi[ks2], w.z, w.w);
        }
    }

    // epilogue
    {
        const int dA = dst[eA], dB = dst[eB];
        const int gFirst = e2g[e0 + 16 * wid];
        const int gLast  = e2g[e0 + 16 * wid + 15];
        float* hA = g_h + (size_t)dA * 32;
        float* hB = g_h + (size_t)dB * 32;
        float* oA = e_out + eA * 32;
        float* oB = e_out + eB * 32;
        float a0[4], a1[4], c0v[4], c1[4];
#pragma unroll
        for (int nb = 0; nb < 4; nb++) {
            const int col = nb * 8 + 2 * t;
            float2 bb = *(const float2*)(b2s + col);
            a0[nb] = d2[nb][0] + bb.x;  a1[nb] = d2[nb][1] + bb.y;
            c0v[nb] = d2[nb][2] + bb.x; c1[nb] = d2[nb][3] + bb.y;
            *(float2*)(oA + col) = make_float2(a0[nb], a1[nb]);
            *(float2*)(oB + col) = make_float2(c0v[nb], c1[nb]);
            red2(hA + col, a0[nb], a1[nb]);
            red2(hB + col, c0v[nb], c1[nb]);
        }
        if (gFirst == gLast) {
#pragma unroll
            for (int nb = 0; nb < 4; nb++) {
                float s0 = a0[nb] + c0v[nb];
                float s1 = a1[nb] + c1[nb];
#pragma unroll
                for (int m = 4; m <= 16; m <<= 1) {
                    s0 += __shfl_xor_sync(0xFFFFFFFFu, s0, m);
                    s1 += __shfl_xor_sync(0xFFFFFFFFu, s1, m);
                }
                if (g == 0) {
                    const int col = nb * 8 + 2 * t;
                    atomicAdd(&Es[gFirst * 32 + col], s0);
                    atomicAdd(&Es[gFirst * 32 + col + 1], s1);
                }
            }
        } else {
#pragma unroll
            for (int nb = 0; nb < 4; nb++) {
                const int col = nb * 8 + 2 * t;
                atomicAdd(&Es[gA * 32 + col], a0[nb]);
                atomicAdd(&Es[gA * 32 + col + 1], a1[nb]);
                atomicAdd(&Es[gB * 32 + col], c0v[nb]);
                atomicAdd(&Es[gB * 32 + col + 1], c1[nb]);
            }
        }
    }
    __syncthreads();
    atomicAdd(&g_ecomb[tid], Es[tid]);
}

// ================== NODE KERNEL + global tail ==================
#define NSM_XHI   0        // 128 x 72 fp16 = 18432
#define NSM_W1F   18432    // 512 uint4 = 8192
#define NSM_W2F   26624    // 256 uint4 = 4096
#define NSM_BIAS  30720    // 2048
#define NSM_B2    32768    // 128
#define NSM_NS    32896    // 1024
#define NSM_TOTAL 33920

__global__ void __launch_bounds__(256, 3) node_kernel(
    const float* __restrict__ node_feat, const float* __restrict__ g_repr,
    const int* __restrict__ n2g, const float* __restrict__ b2,
    const float* __restrict__ Wu1, const float* __restrict__ bu1,
    const float* __restrict__ Wu2, const float* __restrict__ bu2,
    float* __restrict__ n_out, float* __restrict__ g_out)
{
    extern __shared__ unsigned char smem[];
    const int tid = threadIdx.x;
    const int wid = tid >> 5, lid = tid & 31;

    __half* Xhi = (__half*)(smem + NSM_XHI);
    const uint4* W1F = (const uint4*)(smem + NSM_W1F);
    const uint4* W2F = (const uint4*)(smem + NSM_W2F);
    float* Bs  = (float*)(smem + NSM_BIAS);
    float* b2s = (float*)(smem + NSM_B2);
    float* Ns  = (float*)(smem + NSM_NS);

    {
        uint4* d1 = (uint4*)(smem + NSM_W1F);
        for (int i = tid; i < 512; i += 256) d1[i] = gWn1frag[i];
        uint4* d2 = (uint4*)(smem + NSM_W2F);
        if (tid < 256) d2[tid] = gWn2frag[tid];
        for (int i = tid; i < 512; i += 256) Bs[i] = gBias1n[i];
        if (tid < DOUT) b2s[tid] = b2[tid];
        Ns[tid] = 0.f;
    }

    const int n0base = blockIdx.x * 128;

    // gather: k 0..63 = node_feat || g_h
    {
        const int r = tid >> 1, half = tid & 1;
        const int node = n0base + r;
        __half* xh = Xhi + r * 72 + half * 32;
        if (node < N_NODES) {
            const float4* p = (const float4*)((half ? g_h : node_feat) + (size_t)node * 32);
#pragma unroll
            for (int q = 0; q < 4; q++)
                *(uint4*)(xh + q * 8) = cvt8h1(p[2 * q], p[2 * q + 1]);
        } else {
            const uint4 z = make_uint4(0, 0, 0, 0);
#pragma unroll
            for (int q = 0; q < 4; q++) *(uint4*)(xh + q * 8) = z;
        }
    }
    __syncthreads();

    const int g = lid >> 2, t = lid & 3;
    const int r0 = 16 * wid + g;
    float acc[8][4];
#pragma unroll
    for (int n0 = 0; n0 < 8; n0++)
#pragma unroll
        for (int j = 0; j < 4; j++) acc[n0][j] = 0.f;

    gemm_pass<0, 4>(Xhi, W1F, r0, t, lid, acc);

    const int nA = n0base + r0, nB = nA + 8;
    const bool vA = nA < N_NODES, vB = nB < N_NODES;
    const int gA = vA ? n2g[nA] : 0, gB = vB ? n2g[nB] : 0;

    uint32_t Ahi[4][4];
#pragma unroll
    for (int n0 = 0; n0 < 8; n0++) {
        const int col = n0 * 8 + 2 * t;
        float2 bbA = *(const float2*)(Bs + gA * 64 + col);
        float2 bbB = *(const float2*)(Bs + gB * 64 + col);
        const int ks2 = n0 >> 1, ib = (n0 & 1) * 2;
        Ahi[ks2][ib]     = hpack(fmaxf(acc[n0][0] + bbA.x, 0.f),
                                 fmaxf(acc[n0][1] + bbA.y, 0.f));
        Ahi[ks2][ib + 1] = hpack(fmaxf(acc[n0][2] + bbB.x, 0.f),
                                 fmaxf(acc[n0][3] + bbB.y, 0.f));
    }

    float d2[4][4];
#pragma unroll
    for (int nb = 0; nb < 4; nb++)
#pragma unroll
        for (int j = 0; j < 4; j++) d2[nb][j] = 0.f;

#pragma unroll
    for (int ks2 = 0; ks2 < 4; ks2++) {
        const uint4* wf = W2F + (ks2 * 2) * 32 + lid;
#pragma unroll
        for (int p = 0; p < 2; p++) {
            uint4 w = wf[p * 32];
            mma_h(d2[2 * p], Ahi[ks2], w.x, w.y);
            mma_h(d2[2 * p + 1], Ahi[ks2], w.z, w.w);
        }
    }

    // epilogue
    {
        const bool warpFull = (n0base + 16 * wid + 15) < N_NODES;
        int gFirst = 0, gLast = -1;
        if (warpFull) {
            gFirst = n2g[n0base + 16 * wid];
            gLast  = n2g[n0base + 16 * wid + 15];
        }
        float a0[4], a1[4], c0v[4], c1[4];
#pragma unroll
        for (int nb = 0; nb < 4; nb++) {
            const int col = nb * 8 + 2 * t;
            float2 bb = *(const float2*)(b2s + col);
            a0[nb] = d2[nb][0] + bb.x;  a1[nb] = d2[nb][1] + bb.y;
            c0v[nb] = d2[nb][2] + bb.x; c1[nb] = d2[nb][3] + bb.y;
            if (vA) *(float2*)(n_out + (size_t)nA * 32 + col) = make_float2(a0[nb], a1[nb]);
            if (vB) *(float2*)(n_out + (size_t)nB * 32 + col) = make_float2(c0v[nb], c1[nb]);
        }
        if (warpFull && gFirst == gLast) {
#pragma unroll
            for (int nb = 0; nb < 4; nb++) {
                float s0 = a0[nb] + c0v[nb];
                float s1 = a1[nb] + c1[nb];
#pragma unroll
                for (int m = 4; m <= 16; m <<= 1) {
                    s0 += __shfl_xor_sync(0xFFFFFFFFu, s0, m);
                    s1 += __shfl_xor_sync(0xFFFFFFFFu, s1, m);
                }
                if (g == 0) {
                    const int col = nb * 8 + 2 * t;
                    atomicAdd(&Ns[gFirst * 32 + col], s0);
                    atomicAdd(&Ns[gFirst * 32 + col + 1], s1);
                }
            }
        } else {
#pragma unroll
            for (int nb = 0; nb < 4; nb++) {
                const int col = nb * 8 + 2 * t;
                if (vA) {
                    atomicAdd(&Ns[gA * 32 + col], a0[nb]);
                    atomicAdd(&Ns[gA * 32 + col + 1], a1[nb]);
                }
                if (vB) {
                    atomicAdd(&Ns[gB * 32 + col], c0v[nb]);
                    atomicAdd(&Ns[gB * 32 + col + 1], c1[nb]);
                }
            }
        }
    }
    __syncthreads();
    atomicAdd(&g_ncomb[tid], Ns[tid]);

    // -------- last-block global MLP tail --------
    __shared__ unsigned s_done;
    __threadfence();
    __syncthreads();
    if (tid == 0) {
        unsigned tk = atomicAdd(&g_ticket, 1);
        s_done = (tk == gridDim.x - 1) ? 1u : 0u;
    }
    __syncthreads();
    if (!s_done) return;
    __threadfence();

    float* U   = (float*)(smem + 0);        // 768 f
    float* W1u = (float*)(smem + 4096);     // 6144 f
    float* W2u = (float*)(smem + 28672);    // 2048 f -> ends 36864... (33920 total; W2u must fit)
    // NOTE: NSM_TOTAL is 33920; place W2u within bounds instead:
    // reuse BIAS region (30720) for W2u? BIAS is 2048B (512 f) but W2u needs 8192B.
    // Use offsets that fit 33920: U@0 (3072B), W1u@4096 (24576B) ends 28672,
    // W2u@28672 needs 8192 -> ends 36864 > 33920. Shrink: keep W2u in gmem loads.
    __syncthreads();

    for (int i = tid; i < B_GRAPH * 96; i += 256) {
        const int b = i / 96, c = i % 96;
        float v;
        if (c < 32)      v = g_ncomb[b * 32 + c];
        else if (c < 64) v = g_ecomb[b * 32 + (c - 32)];
        else             v = g_repr[b * 32 + (c - 64)];
        U[i] = v;
    }
    {
        const float4* wg = (const float4*)Wu1; float4* ws = (float4*)W1u;
        for (int i = tid; i < 1536; i += 256) ws[i] = wg[i];
    }
    __syncthreads();

    float* Hg = (float*)(smem + 29696);     // 512 f = 2048B, ends 31744 <= 33920
    for (int idx = tid; idx < B_GRAPH * HID; idx += 256) {
        const int b = idx >> 6, j = idx & 63;
        float s = bu1[j];
#pragma unroll 8
        for (int k = 0; k < 96; k++) s += U[b * 96 + k] * W1u[k * 64 + j];
        Hg[idx] = fmaxf(s, 0.f);
    }
    __syncthreads();
    for (int idx = tid; idx < B_GRAPH * DOUT; idx += 256) {
        const int b = idx >> 5, c = idx & 31;
        float s = bu2[c];
#pragma unroll 8
        for (int k = 0; k < 64; k++) s += Hg[b * 64 + k] * Wu2[k * 32 + c];
        g_out[idx] = s;
    }
}

extern "C" void kernel_launch(void* const* d_in, const int* in_sizes, int n_in,
                              void* d_out, int out_size)
{
    const float* edge_feat = (const float*)d_in[0];
    const float* node_feat = (const float*)d_in[1];
    const float* g_repr    = (const float*)d_in[2];
    const int*   src       = (const int*)d_in[3];
    const int*   dst       = (const int*)d_in[4];
    const int*   n2g       = (const int*)d_in[5];
    const int*   e2g       = (const int*)d_in[6];
    const float* W_e1 = (const float*)d_in[7];
    const float* b_e1 = (const float*)d_in[8];
    const float* W_e2 = (const float*)d_in[9];
    const float* b_e2 = (const float*)d_in[10];
    const float* W_n1 = (const float*)d_in[11];
    const float* b_n1 = (const float*)d_in[12];
    const float* W_n2 = (const float*)d_in[13];
    const float* b_n2 = (const float*)d_in[14];
    const float* W_u1 = (const float*)d_in[15];
    const float* b_u1 = (const float*)d_in[16];
    const float* W_u2 = (const float*)d_in[17];
    const float* b_u2 = (const float*)d_in[18];

    float* out = (float*)d_out;
    float* e_out = out;                                      // [E, 32]
    float* n_out = out + (size_t)N_EDGES * DOUT;             // [N, 32]
    float* g_out = out + (size_t)(N_EDGES + N_NODES) * DOUT; // [B, 32]

    cudaFuncSetAttribute(edge_kernel, cudaFuncAttributeMaxDynamicSharedMemorySize, SM_TOTAL);
    cudaFuncSetAttribute(node_kernel, cudaFuncAttributeMaxDynamicSharedMemorySize, NSM_TOTAL);

    zero_kernel<<<ZERO_BLOCKS + 8, 256>>>(W_e1, W_e2, W_n1, W_n2,
                                          b_e1, b_n1, g_repr);
    edge_kernel<<<N_EDGES / 128, 256, SM_TOTAL>>>(
        edge_feat, node_feat, src, dst, e2g, b_e2, e_out);
    node_kernel<<<(N_NODES + 127) / 128, 256, NSM_TOTAL>>>(
        node_feat, g_repr, n2g, b_n2,
        W_u1, b_u1, W_u2, b_u2, n_out, g_out);
}

// round 16
// speedup vs baseline: 1.2104x; 1.0520x over previous
#include <cuda_runtime.h>
#include <cuda_fp16.h>
#include <cstdint>

#define N_NODES 50000
#define N_EDGES 800000
#define B_GRAPH 8
#define HID 64
#define DOUT 32

__device__ __forceinline__ void mma_h(float* d, const uint32_t* a,
                                      uint32_t b0, uint32_t b1) {
    asm volatile(
        "mma.sync.aligned.m16n8k16.row.col.f32.f16.f16.f32 "
        "{%0,%1,%2,%3}, {%4,%5,%6,%7}, {%8,%9}, {%0,%1,%2,%3};"
        : "+f"(d[0]), "+f"(d[1]), "+f"(d[2]), "+f"(d[3])
        : "r"(a[0]), "r"(a[1]), "r"(a[2]), "r"(a[3]), "r"(b0), "r"(b1));
}
__device__ __forceinline__ void red2(float* p, float x, float y) {
    asm volatile("red.global.add.v2.f32 [%0], {%1, %2};"
                 :: "l"(p), "f"(x), "f"(y) : "memory");
}

// -------------------- scratch (device globals) --------------------
__device__ float g_h[(size_t)N_NODES * DOUT];
__device__ float g_ecomb[B_GRAPH * DOUT];
__device__ float g_ncomb[B_GRAPH * DOUT];
__device__ unsigned int g_ticket;
// fp16 hi-only weight fragments; each uint4 = two n-blocks {b0,b1} pairs
__device__ __align__(16) uint4 gW1frag[6 * 4 * 32];   // edge W1 (k 0..95)
__device__ __align__(16) uint4 gW2frag[4 * 2 * 32];   // edge W2
__device__ __align__(16) uint4 gWn1frag[4 * 4 * 32];  // node W1 (k 0..63)
__device__ __align__(16) uint4 gWn2frag[4 * 2 * 32];  // node W2
// per-graph fused biases: b1 + g_repr[g] @ W1[tail]  (exact fp32 fold)
__device__ __align__(16) float gBias1e[B_GRAPH * HID];
__device__ __align__(16) float gBias1n[B_GRAPH * HID];

__device__ __forceinline__ uint32_t hpack(float a, float b) {
    __half2 h = __floats2half2_rn(a, b);
    return *(uint32_t*)&h;
}

// -------------------- zero + prep --------------------
#define ZERO_BLOCKS 391    // 391*256*4 float4 >= 400k float4 (g_h)
#define PSTRIDE 2048       // 8 prep blocks * 256 threads

__global__ void zero_kernel(const float* __restrict__ W1,
                            const float* __restrict__ W2,
                            const float* __restrict__ Wn1,
                            const float* __restrict__ Wn2,
                            const float* __restrict__ b1e,
                            const float* __restrict__ b1n,
                            const float* __restrict__ g_repr) {
    if (blockIdx.x >= ZERO_BLOCKS) {
        const int pidx = (blockIdx.x - ZERO_BLOCKS) * 256 + threadIdx.x;
        if (pidx == 0) g_ticket = 0;
        if (pidx < 64) ((float4*)g_ecomb)[pidx] = make_float4(0.f, 0.f, 0.f, 0.f);
        else if (pidx < 128) ((float4*)g_ncomb)[pidx - 64] = make_float4(0.f, 0.f, 0.f, 0.f);
        // edge W1 fragments (hi-only fp16), k 0..95
        for (int idx = pidx; idx < 768; idx += PSTRIDE) {
            const int l = idx & 31, p = (idx >> 5) & 3, ks = idx >> 7;
            const int ne = p * 16 + (l >> 2), no = ne + 8;
            const int k0 = ks * 16 + 2 * (l & 3);
            uint4 f;
            f.x = hpack(W1[k0 * 64 + ne], W1[(k0 + 1) * 64 + ne]);
            f.y = hpack(W1[(k0 + 8) * 64 + ne], W1[(k0 + 9) * 64 + ne]);
            f.z = hpack(W1[k0 * 64 + no], W1[(k0 + 1) * 64 + no]);
            f.w = hpack(W1[(k0 + 8) * 64 + no], W1[(k0 + 9) * 64 + no]);
            gW1frag[idx] = f;
        }
        for (int idx = pidx; idx < 256; idx += PSTRIDE) {
            const int l = idx & 31, p = (idx >> 5) & 1, ks2 = idx >> 6;
            const int ne = p * 16 + (l >> 2), no = ne + 8;
            const int k0 = ks2 * 16 + 2 * (l & 3);
            uint4 f;
            f.x = hpack(W2[k0 * 32 + ne], W2[(k0 + 1) * 32 + ne]);
            f.y = hpack(W2[(k0 + 8) * 32 + ne], W2[(k0 + 9) * 32 + ne]);
            f.z = hpack(W2[k0 * 32 + no], W2[(k0 + 1) * 32 + no]);
            f.w = hpack(W2[(k0 + 8) * 32 + no], W2[(k0 + 9) * 32 + no]);
            gW2frag[idx] = f;
        }
        for (int idx = pidx; idx < 512; idx += PSTRIDE) {
            const int l = idx & 31, p = (idx >> 5) & 3, ks = idx >> 7;
            const int ne = p * 16 + (l >> 2), no = ne + 8;
            const int k0 = ks * 16 + 2 * (l & 3);
            uint4 f;
            f.x = hpack(Wn1[k0 * 64 + ne], Wn1[(k0 + 1) * 64 + ne]);
            f.y = hpack(Wn1[(k0 + 8) * 64 + ne], Wn1[(k0 + 9) * 64 + ne]);
            f.z = hpack(Wn1[k0 * 64 + no], Wn1[(k0 + 1) * 64 + no]);
            f.w = hpack(Wn1[(k0 + 8) * 64 + no], Wn1[(k0 + 9) * 64 + no]);
            gWn1frag[idx] = f;
        }
        for (int idx = pidx; idx < 256; idx += PSTRIDE) {
            const int l = idx & 31, p = (idx >> 5) & 1, ks2 = idx >> 6;
            const int ne = p * 16 + (l >> 2), no = ne + 8;
            const int k0 = ks2 * 16 + 2 * (l & 3);
            uint4 f;
            f.x = hpack(Wn2[k0 * 32 + ne], Wn2[(k0 + 1) * 32 + ne]);
            f.y = hpack(Wn2[(k0 + 8) * 32 + ne], Wn2[(k0 + 9) * 32 + ne]);
            f.z = hpack(Wn2[k0 * 32 + no], Wn2[(k0 + 1) * 32 + no]);
            f.w = hpack(Wn2[(k0 + 8) * 32 + no], Wn2[(k0 + 9) * 32 + no]);
            gWn2frag[idx] = f;
        }
        // fused per-graph biases (exact fp32)
        for (int idx = pidx; idx < B_GRAPH * HID; idx += PSTRIDE) {
            const int g = idx >> 6, n = idx & 63;
            float se = b1e[n], sn = b1n[n];
            for (int k = 0; k < 32; k++) {
                se += g_repr[g * 32 + k] * W1[(96 + k) * 64 + n];
                sn += g_repr[g * 32 + k] * Wn1[(64 + k) * 64 + n];
            }
            gBias1e[idx] = se;
            gBias1n[idx] = sn;
        }
        return;
    }
    // g_h zero: 4 float4 per thread (MLP=4)
    size_t base = (size_t)blockIdx.x * 1024 + threadIdx.x;
#pragma unroll
    for (int q = 0; q < 4; q++) {
        size_t i = base + q * 256;
        if (i < (size_t)N_NODES * DOUT / 4)
            ((float4*)g_h)[i] = make_float4(0.f, 0.f, 0.f, 0.f);
    }
}

// float8 -> fp16 hi only
__device__ __forceinline__ uint4 cvt8h1(float4 a, float4 b) {
    __half2 h0 = __floats2half2_rn(a.x, a.y);
    __half2 h1 = __floats2half2_rn(a.z, a.w);
    __half2 h2 = __floats2half2_rn(b.x, b.y);
    __half2 h3 = __floats2half2_rn(b.z, b.w);
    uint4 hi;
    hi.x = *(uint32_t*)&h0; hi.y = *(uint32_t*)&h1;
    hi.z = *(uint32_t*)&h2; hi.w = *(uint32_t*)&h3;
    return hi;
}

// X tile GEMM pass over stride-72 fp16 hi buffer; single-term X*Whi.
template<int KS0, int NKS>
__device__ __forceinline__ void gemm_pass(
    const __half* __restrict__ Xhi,
    const uint4* __restrict__ WF, int r0, int t, int lid, float acc[8][4])
{
#pragma unroll
    for (int ksl = 0; ksl < NKS; ksl++) {
        const int c0 = ksl * 16 + 2 * t;
        const __half* xh = Xhi + r0 * 72 + c0;
        uint32_t ah[4];
        ah[0] = *(const uint32_t*)(xh);
        ah[1] = *(const uint32_t*)(xh + 8 * 72);
        ah[2] = *(const uint32_t*)(xh + 8);
        ah[3] = *(const uint32_t*)(xh + 8 * 72 + 8);
        const uint4* wf = WF + ((KS0 + ksl) * 4) * 32 + lid;
#pragma unroll
        for (int p = 0; p < 4; p++) {
            uint4 w = wf[p * 32];
            mma_h(acc[2 * p], ah, w.x, w.y);
            mma_h(acc[2 * p + 1], ah, w.z, w.w);
        }
    }
}

// ================== EDGE KERNEL (single-term fp16, 2 tiles per block) ==================
#define SM_XHI   0        // 128 x 72 fp16 = 18432
#define SM_W1F   18432    // 768 uint4 = 12288
#define SM_W2F   30720    // 256 uint4 = 4096
#define SM_BIAS  34816    // 512 f = 2048
#define SM_B2    36864    // 128
#define SM_ES    36992    // 1024
#define SM_TOTAL 38016

__global__ void __launch_bounds__(256, 3) edge_kernel(
    const float* __restrict__ edge_feat, const float* __restrict__ node_feat,
    const int* __restrict__ src, const int* __restrict__ dst,
    const int* __restrict__ e2g, const float* __restrict__ b2,
    float* __restrict__ e_out)
{
    extern __shared__ unsigned char smem[];
    const int tid = threadIdx.x;
    const int wid = tid >> 5, lid = tid & 31;

    __half* Xhi = (__half*)(smem + SM_XHI);
    const uint4* W1F = (const uint4*)(smem + SM_W1F);
    const uint4* W2F = (const uint4*)(smem + SM_W2F);
    float* Bs  = (float*)(smem + SM_BIAS);
    float* b2s = (float*)(smem + SM_B2);
    float* Es  = (float*)(smem + SM_ES);

    {
        uint4* d1 = (uint4*)(smem + SM_W1F);
        for (int i = tid; i < 768; i += 256) d1[i] = gW1frag[i];
        uint4* d2 = (uint4*)(smem + SM_W2F);
        if (tid < 256) d2[tid] = gW2frag[tid];
        for (int i = tid; i < 512; i += 256) Bs[i] = gBias1e[i];
        if (tid < DOUT) b2s[tid] = b2[tid];
        Es[tid] = 0.f;
    }

    const int r = tid >> 1, half = tid & 1;
    const int g = lid >> 2, t = lid & 3;
    const int r0 = 16 * wid + g;

#pragma unroll 1
    for (int tt = 0; tt < 2; tt++) {
        const size_t e0 = ((size_t)blockIdx.x * 2 + tt) * 128;
        const size_t eg = e0 + r;
        const int si = src[eg], di = dst[eg];

        // prefetch pass-2 gather (node_feat[dst], 16 cols per thread)
        float4 pf[4];
        {
            const float4* pd = (const float4*)(node_feat + (size_t)di * 32) + 4 * half;
            pf[0] = pd[0]; pf[1] = pd[1]; pf[2] = pd[2]; pf[3] = pd[3];
        }

        // gather pass 1: k 0..63 = edge_feat || node_feat[src]
        {
            const float4* p = (const float4*)(half ? node_feat + (size_t)si * 32
                                                   : edge_feat + eg * 32);
            __half* xh = Xhi + r * 72 + half * 32;
#pragma unroll
            for (int q = 0; q < 4; q++)
                *(uint4*)(xh + q * 8) = cvt8h1(p[2 * q], p[2 * q + 1]);
        }
        __syncthreads();

        float acc[8][4];
#pragma unroll
        for (int n0 = 0; n0 < 8; n0++)
#pragma unroll
            for (int j = 0; j < 4; j++) acc[n0][j] = 0.f;

        gemm_pass<0, 4>(Xhi, W1F, r0, t, lid, acc);
        __syncthreads();

        // store pass-2 gather (cols 0..31 now hold k 64..95 = node_feat[dst])
        {
            __half* xh = Xhi + r * 72 + half * 16;
            *(uint4*)(xh)     = cvt8h1(pf[0], pf[1]);
            *(uint4*)(xh + 8) = cvt8h1(pf[2], pf[3]);
        }
        __syncthreads();

        const size_t eA = e0 + r0, eB = eA + 8;
        const int gA = e2g[eA], gB = e2g[eB];

        gemm_pass<4, 2>(Xhi, W1F, r0, t, lid, acc);

        // fused bias + relu -> fp16 A fragments (single-term)
        uint32_t Ahi[4][4];
#pragma unroll
        for (int n0 = 0; n0 < 8; n0++) {
            const int col = n0 * 8 + 2 * t;
            float2 bbA = *(const float2*)(Bs + gA * 64 + col);
            float2 bbB = *(const float2*)(Bs + gB * 64 + col);
            const int ks2 = n0 >> 1, ib = (n0 & 1) * 2;
            Ahi[ks2][ib]     = hpack(fmaxf(acc[n0][0] + bbA.x, 0.f),
                                     fmaxf(acc[n0][1] + bbA.y, 0.f));
            Ahi[ks2][ib + 1] = hpack(fmaxf(acc[n0][2] + bbB.x, 0.f),
                                     fmaxf(acc[n0][3] + bbB.y, 0.f));
        }

        // GEMM2: K=64, single-term, weight fragments from smem
        float d2[4][4];
#pragma unroll
        for (int nb = 0; nb < 4; nb++)
#pragma unroll
            for (int j = 0; j < 4; j++) d2[nb][j] = 0.f;

#pragma unroll
        for (int ks2 = 0; ks2 < 4; ks2++) {
            const uint4* wf = W2F + (ks2 * 2) * 32 + lid;
#pragma unroll
            for (int p = 0; p < 2; p++) {
                uint4 w = wf[p * 32];
                mma_h(d2[2 * p], Ahi[ks2], w.x, w.y);
                mma_h(d2[2 * p + 1], Ahi[ks2], w.z, w.w);
            }
        }

        // epilogue
        {
            const int dA = dst[eA], dB = dst[eB];
            const int gFirst = e2g[e0 + 16 * wid];
            const int gLast  = e2g[e0 + 16 * wid + 15];
            float* hA = g_h + (size_t)dA * 32;
            float* hB = g_h + (size_t)dB * 32;
            float* oA = e_out + eA * 32;
            float* oB = e_out + eB * 32;
            float a0[4], a1[4], c0v[4], c1[4];
#pragma unroll
            for (int nb = 0; nb < 4; nb++) {
                const int col = nb * 8 + 2 * t;
                float2 bb = *(const float2*)(b2s + col);
                a0[nb] = d2[nb][0] + bb.x;  a1[nb] = d2[nb][1] + bb.y;
                c0v[nb] = d2[nb][2] + bb.x; c1[nb] = d2[nb][3] + bb.y;
                *(float2*)(oA + col) = make_float2(a0[nb], a1[nb]);
                *(float2*)(oB + col) = make_float2(c0v[nb], c1[nb]);
                red2(hA + col, a0[nb], a1[nb]);
                red2(hB + col, c0v[nb], c1[nb]);
            }
            if (gFirst == gLast) {
#pragma unroll
                for (int nb = 0; nb < 4; nb++) {
                    float s0 = a0[nb] + c0v[nb];
                    float s1 = a1[nb] + c1[nb];
#pragma unroll
                    for (int m = 4; m <= 16; m <<= 1) {
                        s0 += __shfl_xor_sync(0xFFFFFFFFu, s0, m);
                        s1 += __shfl_xor_sync(0xFFFFFFFFu, s1, m);
                    }
                    if (g == 0) {
                        const int col = nb * 8 + 2 * t;
                        atomicAdd(&Es[gFirst * 32 + col], s0);
                        atomicAdd(&Es[gFirst * 32 + col + 1], s1);
                    }
                }
            } else {
#pragma unroll
                for (int nb = 0; nb < 4; nb++) {
                    const int col = nb * 8 + 2 * t;
                    atomicAdd(&Es[gA * 32 + col], a0[nb]);
                    atomicAdd(&Es[gA * 32 + col + 1], a1[nb]);
                    atomicAdd(&Es[gB * 32 + col], c0v[nb]);
                    atomicAdd(&Es[gB * 32 + col + 1], c1[nb]);
                }
            }
        }
        __syncthreads();   // protects Xhi reuse next tile + Es completeness
    }
    atomicAdd(&g_ecomb[tid], Es[tid]);
}

// ================== NODE KERNEL + global tail ==================
#define NSM_XHI   0        // 128 x 72 fp16 = 18432
#define NSM_W1F   18432    // 512 uint4 = 8192
#define NSM_W2F   26624    // 256 uint4 = 4096
#define NSM_BIAS  30720    // 2048
#define NSM_B2    32768    // 128
#define NSM_NS    32896    // 1024
#define NSM_TOTAL 33920

__global__ void __launch_bounds__(256, 3) node_kernel(
    const float* __restrict__ node_feat, const float* __restrict__ g_repr,
    const int* __restrict__ n2g, const float* __restrict__ b2,
    const float* __restrict__ Wu1, const float* __restrict__ bu1,
    const float* __restrict__ Wu2, const float* __restrict__ bu2,
    float* __restrict__ n_out, float* __restrict__ g_out)
{
    extern __shared__ unsigned char smem[];
    const int tid = threadIdx.x;
    const int wid = tid >> 5, lid = tid & 31;

    __half* Xhi = (__half*)(smem + NSM_XHI);
    const uint4* W1F = (const uint4*)(smem + NSM_W1F);
    const uint4* W2F = (const uint4*)(smem + NSM_W2F);
    float* Bs  = (float*)(smem + NSM_BIAS);
    float* b2s = (float*)(smem + NSM_B2);
    float* Ns  = (float*)(smem + NSM_NS);

    {
        uint4* d1 = (uint4*)(smem + NSM_W1F);
        for (int i = tid; i < 512; i += 256) d1[i] = gWn1frag[i];
        uint4* d2 = (uint4*)(smem + NSM_W2F);
        if (tid < 256) d2[tid] = gWn2frag[tid];
        for (int i = tid; i < 512; i += 256) Bs[i] = gBias1n[i];
        if (tid < DOUT) b2s[tid] = b2[tid];
        Ns[tid] = 0.f;
    }

    const int n0base = blockIdx.x * 128;

    // gather: k 0..63 = node_feat || g_h
    {
        const int r = tid >> 1, half = tid & 1;
        const int node = n0base + r;
        __half* xh = Xhi + r * 72 + half * 32;
        if (node < N_NODES) {
            const float4* p = (const float4*)((half ? g_h : node_feat) + (size_t)node * 32);
#pragma unroll
            for (int q = 0; q < 4; q++)
                *(uint4*)(xh + q * 8) = cvt8h1(p[2 * q], p[2 * q + 1]);
        } else {
            const uint4 z = make_uint4(0, 0, 0, 0);
#pragma unroll
            for (int q = 0; q < 4; q++) *(uint4*)(xh + q * 8) = z;
        }
    }
    __syncthreads();

    const int g = lid >> 2, t = lid & 3;
    const int r0 = 16 * wid + g;
    float acc[8][4];
#pragma unroll
    for (int n0 = 0; n0 < 8; n0++)
#pragma unroll
        for (int j = 0; j < 4; j++) acc[n0][j] = 0.f;

    gemm_pass<0, 4>(Xhi, W1F, r0, t, lid, acc);

    const int nA = n0base + r0, nB = nA + 8;
    const bool vA = nA < N_NODES, vB = nB < N_NODES;
    const int gA = vA ? n2g[nA] : 0, gB = vB ? n2g[nB] : 0;

    uint32_t Ahi[4][4];
#pragma unroll
    for (int n0 = 0; n0 < 8; n0++) {
        const int col = n0 * 8 + 2 * t;
        float2 bbA = *(const float2*)(Bs + gA * 64 + col);
        float2 bbB = *(const float2*)(Bs + gB * 64 + col);
        const int ks2 = n0 >> 1, ib = (n0 & 1) * 2;
        Ahi[ks2][ib]     = hpack(fmaxf(acc[n0][0] + bbA.x, 0.f),
                                 fmaxf(acc[n0][1] + bbA.y, 0.f));
        Ahi[ks2][ib + 1] = hpack(fmaxf(acc[n0][2] + bbB.x, 0.f),
                                 fmaxf(acc[n0][3] + bbB.y, 0.f));
    }

    float d2[4][4];
#pragma unroll
    for (int nb = 0; nb < 4; nb++)
#pragma unroll
        for (int j = 0; j < 4; j++) d2[nb][j] = 0.f;

#pragma unroll
    for (int ks2 = 0; ks2 < 4; ks2++) {
        const uint4* wf = W2F + (ks2 * 2) * 32 + lid;
#pragma unroll
        for (int p = 0; p < 2; p++) {
            uint4 w = wf[p * 32];
            mma_h(d2[2 * p], Ahi[ks2], w.x, w.y);
            mma_h(d2[2 * p + 1], Ahi[ks2], w.z, w.w);
        }
    }

    // epilogue
    {
        const bool warpFull = (n0base + 16 * wid + 15) < N_NODES;
        int gFirst = 0, gLast = -1;
        if (warpFull) {
            gFirst = n2g[n0base + 16 * wid];
            gLast  = n2g[n0base + 16 * wid + 15];
        }
        float a0[4], a1[4], c0v[4], c1[4];
#pragma unroll
        for (int nb = 0; nb < 4; nb++) {
            const int col = nb * 8 + 2 * t;
            float2 bb = *(const float2*)(b2s + col);
            a0[nb] = d2[nb][0] + bb.x;  a1[nb] = d2[nb][1] + bb.y;
            c0v[nb] = d2[nb][2] + bb.x; c1[nb] = d2[nb][3] + bb.y;
            if (vA) *(float2*)(n_out + (size_t)nA * 32 + col) = make_float2(a0[nb], a1[nb]);
            if (vB) *(float2*)(n_out + (size_t)nB * 32 + col) = make_float2(c0v[nb], c1[nb]);
        }
        if (warpFull && gFirst == gLast) {
#pragma unroll
            for (int nb = 0; nb < 4; nb++) {
                float s0 = a0[nb] + c0v[nb];
                float s1 = a1[nb] + c1[nb];
#pragma unroll
                for (int m = 4; m <= 16; m <<= 1) {
                    s0 += __shfl_xor_sync(0xFFFFFFFFu, s0, m);
                    s1 += __shfl_xor_sync(0xFFFFFFFFu, s1, m);
                }
                if (g == 0) {
                    const int col = nb * 8 + 2 * t;
                    atomicAdd(&Ns[gFirst * 32 + col], s0);
                    atomicAdd(&Ns[gFirst * 32 + col + 1], s1);
                }
            }
        } else {
#pragma unroll
            for (int nb = 0; nb < 4; nb++) {
                const int col = nb * 8 + 2 * t;
                if (vA) {
                    atomicAdd(&Ns[gA * 32 + col], a0[nb]);
                    atomicAdd(&Ns[gA * 32 + col + 1], a1[nb]);
                }
                if (vB) {
                    atomicAdd(&Ns[gB * 32 + col], c0v[nb]);
                    atomicAdd(&Ns[gB * 32 + col + 1], c1[nb]);
                }
            }
        }
    }
    __syncthreads();
    atomicAdd(&g_ncomb[tid], Ns[tid]);

    // -------- last-block global MLP tail --------
    __shared__ unsigned s_done;
    __threadfence();
    __syncthreads();
    if (tid == 0) {
        unsigned tk = atomicAdd(&g_ticket, 1);
        s_done = (tk == gridDim.x - 1) ? 1u : 0u;
    }
    __syncthreads();
    if (!s_done) return;
    __threadfence();

    float* U   = (float*)(smem + 0);        // 768 f = 3072B
    float* W1u = (float*)(smem + 4096);     // 6144 f = 24576B, ends 28672
    __syncthreads();

    for (int i = tid; i < B_GRAPH * 96; i += 256) {
        const int b = i / 96, c = i % 96;
        float v;
        if (c < 32)      v = g_ncomb[b * 32 + c];
        else if (c < 64) v = g_ecomb[b * 32 + (c - 32)];
        else             v = g_repr[b * 32 + (c - 64)];
        U[i] = v;
    }
    {
        const float4* wg = (const float4*)Wu1; float4* ws = (float4*)W1u;
        for (int i = tid; i < 1536; i += 256) ws[i] = wg[i];
    }
    __syncthreads();

    float* Hg = (float*)(smem + 29696);     // 512 f = 2048B, ends 31744 <= 33920
    for (int idx = tid; idx < B_GRAPH * HID; idx += 256) {
        const int b = idx >> 6, j = idx & 63;
        float s = bu1[j];
#pragma unroll 8
        for (int k = 0; k < 96; k++) s += U[b * 96 + k] * W1u[k * 64 + j];
        Hg[idx] = fmaxf(s, 0.f);
    }
    __syncthreads();
    for (int idx = tid; idx < B_GRAPH * DOUT; idx += 256) {
        const int b = idx >> 5, c = idx & 31;
        float s = bu2[c];
#pragma unroll 8
        for (int k = 0; k < 64; k++) s += Hg[b * 64 + k] * Wu2[k * 32 + c];
        g_out[idx] = s;
    }
}

extern "C" void kernel_launch(void* const* d_in, const int* in_sizes, int n_in,
                              void* d_out, int out_size)
{
    const float* edge_feat = (const float*)d_in[0];
    const float* node_feat = (const float*)d_in[1];
    const float* g_repr    = (const float*)d_in[2];
    const int*   src       = (const int*)d_in[3];
    const int*   dst       = (const int*)d_in[4];
    const int*   n2g       = (const int*)d_in[5];
    const int*   e2g       = (const int*)d_in[6];
    const float* W_e1 = (const float*)d_in[7];
    const float* b_e1 = (const float*)d_in[8];
    const float* W_e2 = (const float*)d_in[9];
    const float* b_e2 = (const float*)d_in[10];
    const float* W_n1 = (const float*)d_in[11];
    const float* b_n1 = (const float*)d_in[12];
    const float* W_n2 = (const float*)d_in[13];
    const float* b_n2 = (const float*)d_in[14];
    const float* W_u1 = (const float*)d_in[15];
    const float* b_u1 = (const float*)d_in[16];
    const float* W_u2 = (const float*)d_in[17];
    const float* b_u2 = (const float*)d_in[18];

    float* out = (float*)d_out;
    float* e_out = out;                                      // [E, 32]
    float* n_out = out + (size_t)N_EDGES * DOUT;             // [N, 32]
    float* g_out = out + (size_t)(N_EDGES + N_NODES) * DOUT; // [B, 32]

    cudaFuncSetAttribute(edge_kernel, cudaFuncAttributeMaxDynamicSharedMemorySize, SM_TOTAL);
    cudaFuncSetAttribute(node_kernel, cudaFuncAttributeMaxDynamicSharedMemorySize, NSM_TOTAL);

    zero_kernel<<<ZERO_BLOCKS + 8, 256>>>(W_e1, W_e2, W_n1, W_n2,
                                          b_e1, b_n1, g_repr);
    edge_kernel<<<N_EDGES / 256, 256, SM_TOTAL>>>(
        edge_feat, node_feat, src, dst, e2g, b_e2, e_out);
    node_kernel<<<(N_NODES + 127) / 128, 256, NSM_TOTAL>>>(
        node_feat, g_repr, n2g, b_n2,
        W_u1, b_u1, W_u2, b_u2, n_out, g_out);
}